// round 2
// baseline (speedup 1.0000x reference)
#include <cuda_runtime.h>
#include <cuda_bf16.h>
#include <math.h>

// ---- fixed problem shapes ----
#define B_DIM 8
#define L_DIM 1024
#define C_DIM 512
#define NP    1243            // pooled tokens: 441+256+169+121+256
#define NTOK  2267            // NP + L
#define NH    8
#define HD    64
#define LN_EPS 1e-5f

// token offsets within the 1243 pooled tokens
#define OFF_S1 0
#define OFF_S2 441
#define OFF_S3 697
#define OFF_S4 866
#define OFF_MX 987

// ---- static device scratch (no allocations allowed) ----
__device__ float g_P0[B_DIM * NP * C_DIM];     // pooled, pre-conv
__device__ float g_P1[B_DIM * NP * C_DIM];     // post conv-residual
__device__ float g_P2[B_DIM * NP * C_DIM];     // post layernorm
__device__ float g_Q [B_DIM * L_DIM * C_DIM];  // q = m @ Wq
__device__ float g_KV[B_DIM * NTOK * 2 * C_DIM];
__device__ float g_O [B_DIM * L_DIM * C_DIM];  // attention output (pre-Wp)

// =====================================================================
// Adaptive average pooling for the 4 avg branches (n = 21,16,13,11).
// grid: (987, B), block: 512 threads (one per channel).
// x layout: [B, H*W, C] with C contiguous -> coalesced reads over c.
// =====================================================================
__global__ void pool_avg_kernel(const float* __restrict__ x, float* __restrict__ P0)
{
    int tok = blockIdx.x;       // 0..986
    int b   = blockIdx.y;
    int c   = threadIdx.x;      // 0..511

    int t = tok, n;
    if      (t < 441) { n = 21; }
    else if (t < 697) { n = 16; t -= 441; }
    else if (t < 866) { n = 13; t -= 697; }
    else              { n = 11; t -= 866; }

    int p = t / n, q = t - p * n;
    int hs = (p * 64) / n, he = ((p + 1) * 64 + n - 1) / n;
    int ws = (q * 64) / n, we = ((q + 1) * 64 + n - 1) / n;

    float s = 0.f;
    for (int h = hs; h < he; h++) {
        const float* xr = x + (((size_t)b * 4096) + (size_t)h * 64) * C_DIM + c;
        for (int w = ws; w < we; w++)
            s += xr[(size_t)w * C_DIM];
    }
    float inv = 1.f / (float)((he - hs) * (we - ws));
    P0[((size_t)b * NP + tok) * C_DIM + c] = s * inv;
}

// =====================================================================
// Exact 16x16 max pool (4x4 windows). grid: (256, B), block 512.
// =====================================================================
__global__ void pool_max_kernel(const float* __restrict__ x, float* __restrict__ P0)
{
    int t = blockIdx.x;         // 0..255
    int b = blockIdx.y;
    int c = threadIdx.x;

    int p = t >> 4, q = t & 15;
    float mx = -1e30f;
    for (int h = p * 4; h < p * 4 + 4; h++) {
        const float* xr = x + (((size_t)b * 4096) + (size_t)h * 64) * C_DIM + c;
        for (int w = q * 4; w < q * 4 + 4; w++)
            mx = fmaxf(mx, xr[(size_t)w * C_DIM]);
    }
    P0[((size_t)b * NP + OFF_MX + t) * C_DIM + c] = mx;
}

// =====================================================================
// Generic 64x64 tiled SGEMM (K = 512), 256 threads, 4x4 per thread.
//   mode 0: C[r,:] = A[r,:] @ Bw (+ bias)            (rows contiguous)
//   mode 1: conv-residual: rows gathered per-branch from P0 (base A);
//           out = acc + bias + A_row ; scattered into g_P1
//   mode 2: kv gather: rows 0..NP-1 from A (=P2), rest from A2 (=m);
//           out = acc (N = 1024)
// =====================================================================
__global__ void gemm64(const float* __restrict__ A, const float* __restrict__ Bw,
                       const float* __restrict__ bias, const float* __restrict__ A2,
                       float* __restrict__ Cout,
                       int M, int N, int mode, int npix, int tok_off)
{
    const int K = 512;
    __shared__ float As[16][64];   // transposed: As[k][row]
    __shared__ float Bs[16][64];

    int tid  = threadIdx.x;
    int brow = blockIdx.y * 64;
    int bcol = blockIdx.x * 64;

    int la_row = tid >> 2;          // 0..63
    int la_k   = (tid & 3) * 4;     // 0,4,8,12
    int lb_k   = tid >> 4;          // 0..15
    int lb_n   = (tid & 15) * 4;

    int arow = brow + la_row;
    bool ok  = (arow < M);
    const float* Abase = A;
    size_t aoff = 0;
    if (ok) {
        if (mode == 0) {
            aoff = (size_t)arow * K;
        } else if (mode == 1) {
            int b = arow / npix; int t = arow - b * npix;
            aoff = ((size_t)b * NP + tok_off + t) * (size_t)C_DIM;
        } else {
            int b = arow / NTOK; int t = arow - b * NTOK;
            if (t < NP) aoff = ((size_t)b * NP + t) * (size_t)C_DIM;
            else { Abase = A2; aoff = ((size_t)b * L_DIM + (t - NP)) * (size_t)C_DIM; }
        }
    }

    float acc[4][4] = {};
    int ty = tid >> 4, tx = tid & 15;

    for (int k0 = 0; k0 < K; k0 += 16) {
        float4 av = ok ? *(const float4*)(Abase + aoff + k0 + la_k)
                       : make_float4(0.f, 0.f, 0.f, 0.f);
        As[la_k + 0][la_row] = av.x;
        As[la_k + 1][la_row] = av.y;
        As[la_k + 2][la_row] = av.z;
        As[la_k + 3][la_row] = av.w;
        *(float4*)&Bs[lb_k][lb_n] =
            *(const float4*)(Bw + (size_t)(k0 + lb_k) * N + bcol + lb_n);
        __syncthreads();

#pragma unroll
        for (int kk = 0; kk < 16; kk++) {
            float a[4], bb[4];
            *(float4*)a  = *(const float4*)&As[kk][ty * 4];
            *(float4*)bb = *(const float4*)&Bs[kk][tx * 4];
#pragma unroll
            for (int i = 0; i < 4; i++)
#pragma unroll
                for (int j = 0; j < 4; j++)
                    acc[i][j] += a[i] * bb[j];
        }
        __syncthreads();
    }

    int col = bcol + tx * 4;
#pragma unroll
    for (int i = 0; i < 4; i++) {
        int r = brow + ty * 4 + i;
        if (r >= M) continue;
        float4 o;
        o.x = acc[i][0]; o.y = acc[i][1]; o.z = acc[i][2]; o.w = acc[i][3];
        if (mode == 1) {
            int b = r / npix; int t = r - b * npix;
            size_t g = ((size_t)b * NP + tok_off + t) * (size_t)C_DIM;
            float4 res = *(const float4*)&A[g + col];
            o.x += res.x + bias[col + 0];
            o.y += res.y + bias[col + 1];
            o.z += res.z + bias[col + 2];
            o.w += res.w + bias[col + 3];
            *(float4*)&Cout[g + col] = o;
        } else {
            if (bias) {
                o.x += bias[col + 0]; o.y += bias[col + 1];
                o.z += bias[col + 2]; o.w += bias[col + 3];
            }
            *(float4*)&Cout[(size_t)r * N + col] = o;
        }
    }
}

// =====================================================================
// Copy the mx branch (pre-LN, post conv-res) to d_out[B,C,16,16].
// =====================================================================
__global__ void mx_copy_kernel(const float* __restrict__ P1, float* __restrict__ out2)
{
    int idx = blockIdx.x * blockDim.x + threadIdx.x;
    if (idx >= B_DIM * C_DIM * 256) return;
    int t = idx & 255;
    int c = (idx >> 8) & 511;
    int b = idx >> 17;
    out2[idx] = P1[(((size_t)b * NP) + OFF_MX + t) * C_DIM + c];
}

// =====================================================================
// LayerNorm over C=512. One block (128 threads, float4 each) per token.
// =====================================================================
__global__ void ln_kernel(const float* __restrict__ X, const float* __restrict__ g,
                          const float* __restrict__ be, float* __restrict__ Y)
{
    int row = blockIdx.x;
    int tid = threadIdx.x;                 // 0..127
    const float4* xr = (const float4*)(X + (size_t)row * C_DIM);
    float4 v = xr[tid];
    float s  = v.x + v.y + v.z + v.w;
    float s2 = v.x * v.x + v.y * v.y + v.z * v.z + v.w * v.w;
#pragma unroll
    for (int o = 16; o >= 1; o >>= 1) {
        s  += __shfl_xor_sync(0xffffffffu, s,  o);
        s2 += __shfl_xor_sync(0xffffffffu, s2, o);
    }
    __shared__ float ws[4], ws2[4];
    int wid = tid >> 5, lane = tid & 31;
    if (lane == 0) { ws[wid] = s; ws2[wid] = s2; }
    __syncthreads();
    float ts  = ws[0]  + ws[1]  + ws[2]  + ws[3];
    float ts2 = ws2[0] + ws2[1] + ws2[2] + ws2[3];
    float mean = ts * (1.f / C_DIM);
    float var  = ts2 * (1.f / C_DIM) - mean * mean;
    float rstd = rsqrtf(var + LN_EPS);
    float4 gg = ((const float4*)g)[tid];
    float4 bb = ((const float4*)be)[tid];
    float4 o;
    o.x = (v.x - mean) * rstd * gg.x + bb.x;
    o.y = (v.y - mean) * rstd * gg.y + bb.y;
    o.z = (v.z - mean) * rstd * gg.z + bb.z;
    o.w = (v.w - mean) * rstd * gg.w + bb.w;
    ((float4*)(Y + (size_t)row * C_DIM))[tid] = o;
}

// =====================================================================
// Fused attention: per (b, h, 64-query tile), flash-style over 36 key
// tiles of 64. 256 threads, each owns a 4x4 patch of the 64x64 S tile
// and a 4(row)x4(dim) patch of the output accumulator.
// smem: Qs[64][64], KsT[64][68] (d-major, reused for P), Vs[64][64].
// =====================================================================
#define ATT_SMEM ((64 * 64 + 64 * 68 + 64 * 64) * 4)

__global__ void attn_kernel(const float* __restrict__ Q, const float* __restrict__ KV,
                            float* __restrict__ O)
{
    extern __shared__ float sm[];
    float* Qs  = sm;                 // [64][64]
    float* KsT = sm + 64 * 64;       // [64][68], d-major; reused as P[r][c]
    float* Vs  = KsT + 64 * 68;      // [64][64]

    int tid = threadIdx.x;
    int b = blockIdx.z, h = blockIdx.y, l0 = blockIdx.x * 64;
    int ty = tid >> 4, tx = tid & 15;

    // load Q tile [64 rows][64 dims]
#pragma unroll
    for (int it = 0; it < 4; it++) {
        int row  = (tid >> 4) + it * 16;
        int col4 = (tid & 15) * 4;
        float4 v = *(const float4*)&Q[(((size_t)b * L_DIM) + l0 + row) * C_DIM + h * HD + col4];
        *(float4*)&Qs[row * 64 + col4] = v;
    }

    float acc[4][4] = {};
    float mrow[4] = {-1e30f, -1e30f, -1e30f, -1e30f};
    float lrow[4] = {0.f, 0.f, 0.f, 0.f};
    const float scale = 0.125f;   // 64^-0.5

    for (int kt = 0; kt < 36; kt++) {
        int kbase = kt * 64;
        __syncthreads();  // previous iter done reading KsT(P)/Vs; also orders Q stores

        // load K (transposed into KsT) and V (natural) for this tile
#pragma unroll
        for (int it = 0; it < 4; it++) {
            int row  = (tid >> 4) + it * 16;     // key within tile
            int col4 = (tid & 15) * 4;           // dim offset
            int kg = kbase + row;
            float4 kv4 = make_float4(0.f, 0.f, 0.f, 0.f);
            float4 vv4 = make_float4(0.f, 0.f, 0.f, 0.f);
            if (kg < NTOK) {
                size_t base = (((size_t)b * NTOK) + kg) * (size_t)(2 * C_DIM) + h * HD + col4;
                kv4 = *(const float4*)&KV[base];
                vv4 = *(const float4*)&KV[base + C_DIM];
            }
            KsT[(col4 + 0) * 68 + row] = kv4.x;
            KsT[(col4 + 1) * 68 + row] = kv4.y;
            KsT[(col4 + 2) * 68 + row] = kv4.z;
            KsT[(col4 + 3) * 68 + row] = kv4.w;
            *(float4*)&Vs[row * 64 + col4] = vv4;
        }
        __syncthreads();

        // S = Q K^T for my 4x4 patch
        float s[4][4] = {};
#pragma unroll 8
        for (int d = 0; d < 64; d++) {
            float4 kb = *(const float4*)&KsT[d * 68 + (tx << 2)];
            float q0 = Qs[(ty * 4 + 0) * 64 + d];
            float q1 = Qs[(ty * 4 + 1) * 64 + d];
            float q2 = Qs[(ty * 4 + 2) * 64 + d];
            float q3 = Qs[(ty * 4 + 3) * 64 + d];
            s[0][0] += q0 * kb.x; s[0][1] += q0 * kb.y; s[0][2] += q0 * kb.z; s[0][3] += q0 * kb.w;
            s[1][0] += q1 * kb.x; s[1][1] += q1 * kb.y; s[1][2] += q1 * kb.z; s[1][3] += q1 * kb.w;
            s[2][0] += q2 * kb.x; s[2][1] += q2 * kb.y; s[2][2] += q2 * kb.z; s[2][3] += q2 * kb.w;
            s[3][0] += q3 * kb.x; s[3][1] += q3 * kb.y; s[3][2] += q3 * kb.z; s[3][3] += q3 * kb.w;
        }

        // mask + scale, online softmax statistics (16-lane row groups)
        float tmax[4];
#pragma unroll
        for (int i = 0; i < 4; i++) {
            tmax[i] = -1e30f;
#pragma unroll
            for (int j = 0; j < 4; j++) {
                int cg = kbase + (tx << 2) + j;
                s[i][j] = (cg < NTOK) ? s[i][j] * scale : -1e30f;
                tmax[i] = fmaxf(tmax[i], s[i][j]);
            }
        }
#pragma unroll
        for (int i = 0; i < 4; i++) {
#pragma unroll
            for (int o = 8; o >= 1; o >>= 1)
                tmax[i] = fmaxf(tmax[i], __shfl_xor_sync(0xffffffffu, tmax[i], o));
        }
        float rsum[4];
#pragma unroll
        for (int i = 0; i < 4; i++) {
            float mnew  = fmaxf(mrow[i], tmax[i]);
            float alpha = __expf(mrow[i] - mnew);
            mrow[i] = mnew;
            float rs = 0.f;
#pragma unroll
            for (int j = 0; j < 4; j++) {
                float p = (s[i][j] > -1e29f) ? __expf(s[i][j] - mnew) : 0.f;
                s[i][j] = p;
                rs += p;
            }
            rsum[i] = rs;
            lrow[i] = lrow[i] * alpha;
#pragma unroll
            for (int j = 0; j < 4; j++) acc[i][j] *= alpha;
        }
#pragma unroll
        for (int i = 0; i < 4; i++) {
#pragma unroll
            for (int o = 8; o >= 1; o >>= 1)
                rsum[i] += __shfl_xor_sync(0xffffffffu, rsum[i], o);
            lrow[i] += rsum[i];
        }

        __syncthreads();  // everyone done reading KsT before P overwrite
        // write P[r][c] into KsT space (stride 68)
#pragma unroll
        for (int i = 0; i < 4; i++)
#pragma unroll
            for (int j = 0; j < 4; j++)
                KsT[(ty * 4 + i) * 68 + (tx << 2) + j] = s[i][j];
        __syncthreads();

        // O += P @ V   (my rows x my dims)
#pragma unroll 8
        for (int c = 0; c < 64; c++) {
            float4 v4 = *(const float4*)&Vs[c * 64 + (tx << 2)];
            float p0 = KsT[(ty * 4 + 0) * 68 + c];
            float p1 = KsT[(ty * 4 + 1) * 68 + c];
            float p2 = KsT[(ty * 4 + 2) * 68 + c];
            float p3 = KsT[(ty * 4 + 3) * 68 + c];
            acc[0][0] += p0 * v4.x; acc[0][1] += p0 * v4.y; acc[0][2] += p0 * v4.z; acc[0][3] += p0 * v4.w;
            acc[1][0] += p1 * v4.x; acc[1][1] += p1 * v4.y; acc[1][2] += p1 * v4.z; acc[1][3] += p1 * v4.w;
            acc[2][0] += p2 * v4.x; acc[2][1] += p2 * v4.y; acc[2][2] += p2 * v4.z; acc[2][3] += p2 * v4.w;
            acc[3][0] += p3 * v4.x; acc[3][1] += p3 * v4.y; acc[3][2] += p3 * v4.z; acc[3][3] += p3 * v4.w;
        }
    }

    // normalize + store: O[b, l, h*64 + dd]
#pragma unroll
    for (int i = 0; i < 4; i++) {
        float inv = 1.f / lrow[i];
        int row = l0 + ty * 4 + i;
        float4 o;
        o.x = acc[i][0] * inv; o.y = acc[i][1] * inv;
        o.z = acc[i][2] * inv; o.w = acc[i][3] * inv;
        *(float4*)&O[(((size_t)b * L_DIM) + row) * C_DIM + h * HD + (tx << 2)] = o;
    }
}

// =====================================================================
// launch
// =====================================================================
extern "C" void kernel_launch(void* const* d_in, const int* in_sizes, int n_in,
                              void* d_out, int out_size)
{
    const float* x    = (const float*)d_in[0];
    const float* m    = (const float*)d_in[1];
    const float* w_s1 = (const float*)d_in[2];
    const float* b_s1 = (const float*)d_in[3];
    const float* w_s2 = (const float*)d_in[4];
    const float* b_s2 = (const float*)d_in[5];
    const float* w_s3 = (const float*)d_in[6];
    const float* b_s3 = (const float*)d_in[7];
    const float* w_s4 = (const float*)d_in[8];
    const float* b_s4 = (const float*)d_in[9];
    const float* w_mx = (const float*)d_in[10];
    const float* b_mx = (const float*)d_in[11];
    const float* ln_g = (const float*)d_in[12];
    const float* ln_b = (const float*)d_in[13];
    const float* Wq   = (const float*)d_in[14];
    const float* Wkv  = (const float*)d_in[15];
    const float* Wp   = (const float*)d_in[16];
    const float* bp   = (const float*)d_in[17];
    float* out  = (float*)d_out;                       // [B,L,C]
    float* out2 = (float*)d_out + (size_t)B_DIM * L_DIM * C_DIM;  // [B,C,16,16]

    float *P0, *P1, *P2, *Qb, *KVb, *Ob;
    cudaGetSymbolAddress((void**)&P0,  g_P0);
    cudaGetSymbolAddress((void**)&P1,  g_P1);
    cudaGetSymbolAddress((void**)&P2,  g_P2);
    cudaGetSymbolAddress((void**)&Qb,  g_Q);
    cudaGetSymbolAddress((void**)&KVb, g_KV);
    cudaGetSymbolAddress((void**)&Ob,  g_O);

    static bool attr_done = false;
    if (!attr_done) {
        cudaFuncSetAttribute(attn_kernel, cudaFuncAttributeMaxDynamicSharedMemorySize, ATT_SMEM);
        attr_done = true;
    }

    // 1) pooling
    pool_avg_kernel<<<dim3(987, B_DIM), 512>>>(x, P0);
    pool_max_kernel<<<dim3(256, B_DIM), 512>>>(x, P0);

    // 2) conv-residual per branch (mode 1)
    struct { const float *w, *b; int npix, off; } br[5] = {
        { w_s1, b_s1, 441, OFF_S1 },
        { w_s2, b_s2, 256, OFF_S2 },
        { w_s3, b_s3, 169, OFF_S3 },
        { w_s4, b_s4, 121, OFF_S4 },
        { w_mx, b_mx, 256, OFF_MX },
    };
    for (int i = 0; i < 5; i++) {
        int M = B_DIM * br[i].npix;
        gemm64<<<dim3(C_DIM / 64, (M + 63) / 64), 256>>>(
            P0, br[i].w, br[i].b, nullptr, P1, M, C_DIM, 1, br[i].npix, br[i].off);
    }

    // 3) mx output (pre-LN) to d_out second chunk
    mx_copy_kernel<<<(B_DIM * C_DIM * 256 + 255) / 256, 256>>>(P1, out2);

    // 4) layernorm over pooled tokens
    ln_kernel<<<B_DIM * NP, 128>>>(P1, ln_g, ln_b, P2);

    // 5) q = m @ Wq
    gemm64<<<dim3(C_DIM / 64, (B_DIM * L_DIM) / 64), 256>>>(
        m, Wq, nullptr, nullptr, Qb, B_DIM * L_DIM, C_DIM, 0, 0, 0);

    // 6) kv = [p; m] @ Wkv   (mode 2 row gather)
    {
        int M = B_DIM * NTOK;
        gemm64<<<dim3((2 * C_DIM) / 64, (M + 63) / 64), 256>>>(
            P2, Wkv, nullptr, m, KVb, M, 2 * C_DIM, 2, 0, 0);
    }

    // 7) fused attention
    attn_kernel<<<dim3(L_DIM / 64, NH, B_DIM), 256, ATT_SMEM>>>(Qb, KVb, Ob);

    // 8) out = O @ Wp + bp
    gemm64<<<dim3(C_DIM / 64, (B_DIM * L_DIM) / 64), 256>>>(
        Ob, Wp, bp, nullptr, out, B_DIM * L_DIM, C_DIM, 0, 0, 0);
}

// round 4
// speedup vs baseline: 1.2442x; 1.2442x over previous
#include <cuda_runtime.h>
#include <cuda_bf16.h>
#include <mma.h>
#include <math.h>
#include <cstdint>

using namespace nvcuda;

#define B_DIM 8
#define L_DIM 1024
#define C_DIM 512
#define NP    1243
#define NTOK  2267
#define NH    8
#define HD    64
#define LN_EPS 1e-5f
#define OFF_MX 987

// ---------------- scratch ----------------
__device__ __align__(128) float g_P0[B_DIM * NP * C_DIM];
__device__ __align__(128) float g_P1[B_DIM * NP * C_DIM];
__device__ __align__(128) float g_Q [B_DIM * L_DIM * C_DIM];
__device__ __align__(128) float g_KV[B_DIM * NTOK * 2 * C_DIM];
__device__ __align__(128) __nv_bfloat16 g_P0h[B_DIM * NP * C_DIM],    g_P0l[B_DIM * NP * C_DIM];
__device__ __align__(128) __nv_bfloat16 g_P2h[B_DIM * NP * C_DIM],    g_P2l[B_DIM * NP * C_DIM];
__device__ __align__(128) __nv_bfloat16 g_mh [B_DIM * L_DIM * C_DIM], g_ml [B_DIM * L_DIM * C_DIM];
__device__ __align__(128) __nv_bfloat16 g_Oh [B_DIM * L_DIM * C_DIM], g_Ol [B_DIM * L_DIM * C_DIM];
#define WSLOT (512 * 512)
__device__ __align__(128) __nv_bfloat16 g_Wth[7 * WSLOT + 512 * 1024], g_Wtl[7 * WSLOT + 512 * 1024];

// ---------------- small helpers ----------------
__device__ __forceinline__ uint32_t smem_u32(const void* p) {
    uint32_t a;
    asm("{ .reg .u64 t; cvta.to.shared.u64 t, %1; cvt.u32.u64 %0, t; }" : "=r"(a) : "l"(p));
    return a;
}
__device__ __forceinline__ void cp16(uint32_t dst, const void* src) {
    asm volatile("cp.async.cg.shared.global [%0], [%1], 16;" :: "r"(dst), "l"(src) : "memory");
}
#define CP_COMMIT() asm volatile("cp.async.commit_group;" ::: "memory")
#define CP_WAIT1()  asm volatile("cp.async.wait_group 1;" ::: "memory")
#define CP_WAIT0()  asm volatile("cp.async.wait_group 0;" ::: "memory")

// ---------------- weight transpose + split: W[512][N] -> T[N][512] hi/lo ----------------
__global__ void wsplit_kernel(const float* __restrict__ W, __nv_bfloat16* __restrict__ Th,
                              __nv_bfloat16* __restrict__ Tl, int N)
{
    __shared__ float t[32][33];
    int n0 = blockIdx.x * 32, k0 = blockIdx.y * 32;
    int tx = threadIdx.x, ty = threadIdx.y;
    for (int i = ty; i < 32; i += 8) t[i][tx] = W[(size_t)(k0 + i) * N + n0 + tx];
    __syncthreads();
    for (int i = ty; i < 32; i += 8) {
        float v = t[tx][i];
        __nv_bfloat16 h = __float2bfloat16(v);
        size_t o = (size_t)(n0 + i) * 512 + k0 + tx;
        Th[o] = h; Tl[o] = __float2bfloat16(v - __bfloat162float(h));
    }
}

__global__ void mcvt_kernel(const float* __restrict__ m, __nv_bfloat16* __restrict__ mh,
                            __nv_bfloat16* __restrict__ ml)
{
    int i = blockIdx.x * blockDim.x + threadIdx.x;
    if (i >= B_DIM * L_DIM * C_DIM) return;
    float v = m[i];
    __nv_bfloat16 h = __float2bfloat16(v);
    mh[i] = h; ml[i] = __float2bfloat16(v - __bfloat162float(h));
}

// ---------------- pooling ----------------
__global__ void pool_avg_kernel(const float* __restrict__ x, float* __restrict__ P0,
                                __nv_bfloat16* __restrict__ Ph, __nv_bfloat16* __restrict__ Pl)
{
    int tok = blockIdx.x, b = blockIdx.y, c = threadIdx.x;
    int t = tok, n;
    if      (t < 441) { n = 21; }
    else if (t < 697) { n = 16; t -= 441; }
    else if (t < 866) { n = 13; t -= 697; }
    else              { n = 11; t -= 866; }
    int p = t / n, q = t - p * n;
    int hs = (p * 64) / n, he = ((p + 1) * 64 + n - 1) / n;
    int ws = (q * 64) / n, we = ((q + 1) * 64 + n - 1) / n;
    float s = 0.f;
    for (int h = hs; h < he; h++) {
        const float* xr = x + (((size_t)b * 4096) + (size_t)h * 64) * C_DIM + c;
        for (int w = ws; w < we; w++) s += xr[(size_t)w * C_DIM];
    }
    float v = s / (float)((he - hs) * (we - ws));
    size_t o = ((size_t)b * NP + tok) * C_DIM + c;
    P0[o] = v;
    __nv_bfloat16 h16 = __float2bfloat16(v);
    Ph[o] = h16; Pl[o] = __float2bfloat16(v - __bfloat162float(h16));
}

__global__ void pool_max_kernel(const float* __restrict__ x, float* __restrict__ P0,
                                __nv_bfloat16* __restrict__ Ph, __nv_bfloat16* __restrict__ Pl)
{
    int t = blockIdx.x, b = blockIdx.y, c = threadIdx.x;
    int p = t >> 4, q = t & 15;
    float mx = -1e30f;
    for (int h = p * 4; h < p * 4 + 4; h++) {
        const float* xr = x + (((size_t)b * 4096) + (size_t)h * 64) * C_DIM + c;
        for (int w = q * 4; w < q * 4 + 4; w++) mx = fmaxf(mx, xr[(size_t)w * C_DIM]);
    }
    size_t o = ((size_t)b * NP + OFF_MX + t) * C_DIM + c;
    P0[o] = mx;
    __nv_bfloat16 h16 = __float2bfloat16(mx);
    Ph[o] = h16; Pl[o] = __float2bfloat16(mx - __bfloat162float(h16));
}

// =====================================================================
// wmma bf16x3 GEMM: 128x128 block tile, K = 512, chunks of 32,
// double-buffered cp.async.  8 warps, warp tile 64(m) x 32(n).
// smem: [0,16) misc, [16,2064) row ptr table, stages at 4096 (2 x 40960).
// Stage layout (bf16, pitch 40): Ah[128][40] Al Bh Bl (10240B each).
// Epilogue stages C (f32, pitch 136) over the stage region.
// =====================================================================
#define STG0    4096
#define STG_SZ  40960
#define TG_SMEM (4096 + 2 * 40960)
#define CPITCH  136

__global__ __launch_bounds__(256) void tgemm_kernel(
    const __nv_bfloat16* __restrict__ Ah, const __nv_bfloat16* __restrict__ Al,
    const __nv_bfloat16* __restrict__ A2h, const __nv_bfloat16* __restrict__ A2l,
    const __nv_bfloat16* __restrict__ Bh, const __nv_bfloat16* __restrict__ Bl,
    const float* __restrict__ bias, const float* __restrict__ resid,
    float* __restrict__ Cout, int M, int N, int mode, int npix, int tok_off)
{
    extern __shared__ char sm_raw[];
    const __nv_bfloat16** aptrs = (const __nv_bfloat16**)(sm_raw + 16);
    uint32_t sb = smem_u32(sm_raw);

    int tid = threadIdx.x;
    int brow = blockIdx.y * 128, bcol = blockIdx.x * 128;

    // per-row A source pointers (gather)
    if (tid < 128) {
        int arow = brow + tid;
        if (arow >= M) arow = M - 1;
        const __nv_bfloat16 *ph, *pl;
        if (mode == 0) {
            size_t o = (size_t)arow * 512; ph = Ah + o; pl = Al + o;
        } else if (mode == 1) {
            int b = arow / npix, t = arow - (arow / npix) * npix;
            size_t o = ((size_t)b * NP + tok_off + t) * 512; ph = Ah + o; pl = Al + o;
        } else {
            int b = arow / NTOK, t = arow - (arow / NTOK) * NTOK;
            if (t < NP) { size_t o = ((size_t)b * NP + t) * 512; ph = Ah + o; pl = Al + o; }
            else        { size_t o = ((size_t)b * L_DIM + (t - NP)) * 512; ph = A2h + o; pl = A2l + o; }
        }
        aptrs[tid] = ph; aptrs[128 + tid] = pl;
    }
    __syncthreads();

    int wid = tid >> 5;
    int wm = wid & 1;       // 0..1 -> rows wm*64
    int wn = wid >> 1;      // 0..3 -> cols wn*32

    wmma::fragment<wmma::accumulator, 16, 16, 16, float> acc[4][2];
#pragma unroll
    for (int mi = 0; mi < 4; mi++)
#pragma unroll
        for (int ni = 0; ni < 2; ni++)
            wmma::fill_fragment(acc[mi][ni], 0.f);

    // ---- issue stage 0 ----
    {
        uint32_t st = sb + STG0;
#pragma unroll
        for (int w = 0; w < 8; w++) {
            int ci = tid + w * 256;
            int region = ci >> 9, idx = ci & 511;
            int row = idx >> 2, ch = idx & 3;
            const __nv_bfloat16* src;
            if (region < 2) src = aptrs[region * 128 + row] + ch * 8;
            else            src = ((region == 2) ? Bh : Bl) + (size_t)(bcol + row) * 512 + ch * 8;
            cp16(st + region * 10240 + row * 80 + ch * 16, src);
        }
        CP_COMMIT();
    }

    for (int j = 0; j < 16; j++) {
        if (j + 1 < 16) {
            uint32_t st = sb + STG0 + ((j + 1) & 1) * STG_SZ;
            int koff = (j + 1) * 32;
#pragma unroll
            for (int w = 0; w < 8; w++) {
                int ci = tid + w * 256;
                int region = ci >> 9, idx = ci & 511;
                int row = idx >> 2, ch = idx & 3;
                const __nv_bfloat16* src;
                if (region < 2) src = aptrs[region * 128 + row] + koff + ch * 8;
                else            src = ((region == 2) ? Bh : Bl) + (size_t)(bcol + row) * 512 + koff + ch * 8;
                cp16(st + region * 10240 + row * 80 + ch * 16, src);
            }
            CP_COMMIT();
            CP_WAIT1();
        } else {
            CP_WAIT0();
        }
        __syncthreads();

        const __nv_bfloat16* st = (const __nv_bfloat16*)(sm_raw + STG0 + (j & 1) * STG_SZ);
        const __nv_bfloat16* As_h = st;
        const __nv_bfloat16* As_l = st + 5120;
        const __nv_bfloat16* Bs_h = st + 10240;
        const __nv_bfloat16* Bs_l = st + 15360;

#pragma unroll
        for (int kk = 0; kk < 2; kk++) {
            wmma::fragment<wmma::matrix_a, 16, 16, 16, __nv_bfloat16, wmma::row_major> fah[4], fal[4];
            wmma::fragment<wmma::matrix_b, 16, 16, 16, __nv_bfloat16, wmma::col_major> fbh[2], fbl[2];
#pragma unroll
            for (int mi = 0; mi < 4; mi++) {
                int r = wm * 64 + mi * 16;
                wmma::load_matrix_sync(fah[mi], As_h + r * 40 + kk * 16, 40);
                wmma::load_matrix_sync(fal[mi], As_l + r * 40 + kk * 16, 40);
            }
#pragma unroll
            for (int ni = 0; ni < 2; ni++) {
                int c = wn * 32 + ni * 16;
                wmma::load_matrix_sync(fbh[ni], Bs_h + c * 40 + kk * 16, 40);
                wmma::load_matrix_sync(fbl[ni], Bs_l + c * 40 + kk * 16, 40);
            }
#pragma unroll
            for (int mi = 0; mi < 4; mi++)
#pragma unroll
                for (int ni = 0; ni < 2; ni++) {
                    wmma::mma_sync(acc[mi][ni], fah[mi], fbh[ni], acc[mi][ni]);
                    wmma::mma_sync(acc[mi][ni], fah[mi], fbl[ni], acc[mi][ni]);
                    wmma::mma_sync(acc[mi][ni], fal[mi], fbh[ni], acc[mi][ni]);
                }
        }
        __syncthreads();
    }

    // ---- epilogue: stage C in smem then gather/bias/residual ----
    float* Cs = (float*)(sm_raw + STG0);
#pragma unroll
    for (int mi = 0; mi < 4; mi++)
#pragma unroll
        for (int ni = 0; ni < 2; ni++)
            wmma::store_matrix_sync(Cs + (wm * 64 + mi * 16) * CPITCH + wn * 32 + ni * 16,
                                    acc[mi][ni], CPITCH, wmma::mem_row_major);
    __syncthreads();

    int lane = tid & 31, wrow = tid >> 5;
    for (int rr = wrow; rr < 128; rr += 8) {
        int r = brow + rr;
        if (r >= M) continue;
        int col0 = lane * 4;
        float4 o = *(float4*)&Cs[rr * CPITCH + col0];
        int col = bcol + col0;
        if (bias) {
            o.x += bias[col];     o.y += bias[col + 1];
            o.z += bias[col + 2]; o.w += bias[col + 3];
        }
        if (mode == 1) {
            int b = r / npix, t = r - (r / npix) * npix;
            size_t g = ((size_t)b * NP + tok_off + t) * 512;
            float4 rv = *(const float4*)&resid[g + col];
            o.x += rv.x; o.y += rv.y; o.z += rv.z; o.w += rv.w;
            *(float4*)&Cout[g + col] = o;
        } else {
            *(float4*)&Cout[(size_t)r * N + col] = o;
        }
    }
}

// ---------------- mx copy ----------------
__global__ void mx_copy_kernel(const float* __restrict__ P1, float* __restrict__ out2)
{
    int idx = blockIdx.x * blockDim.x + threadIdx.x;
    if (idx >= B_DIM * C_DIM * 256) return;
    int t = idx & 255, c = (idx >> 8) & 511, b = idx >> 17;
    out2[idx] = P1[(((size_t)b * NP) + OFF_MX + t) * C_DIM + c];
}

// ---------------- layernorm -> bf16 hi/lo ----------------
__global__ void ln_kernel(const float* __restrict__ X, const float* __restrict__ g,
                          const float* __restrict__ be,
                          __nv_bfloat16* __restrict__ Yh, __nv_bfloat16* __restrict__ Yl)
{
    int row = blockIdx.x, tid = threadIdx.x;
    float4 v = ((const float4*)(X + (size_t)row * C_DIM))[tid];
    float s  = v.x + v.y + v.z + v.w;
    float s2 = v.x * v.x + v.y * v.y + v.z * v.z + v.w * v.w;
#pragma unroll
    for (int o = 16; o >= 1; o >>= 1) {
        s  += __shfl_xor_sync(0xffffffffu, s,  o);
        s2 += __shfl_xor_sync(0xffffffffu, s2, o);
    }
    __shared__ float ws[4], ws2[4];
    int wid = tid >> 5, lane = tid & 31;
    if (lane == 0) { ws[wid] = s; ws2[wid] = s2; }
    __syncthreads();
    float ts = ws[0] + ws[1] + ws[2] + ws[3], ts2 = ws2[0] + ws2[1] + ws2[2] + ws2[3];
    float mean = ts * (1.f / C_DIM);
    float var  = ts2 * (1.f / C_DIM) - mean * mean;
    float rstd = rsqrtf(var + LN_EPS);
    float4 gg = ((const float4*)g)[tid], bb = ((const float4*)be)[tid];
    float y[4] = { (v.x - mean) * rstd * gg.x + bb.x, (v.y - mean) * rstd * gg.y + bb.y,
                   (v.z - mean) * rstd * gg.z + bb.z, (v.w - mean) * rstd * gg.w + bb.w };
    size_t o = (size_t)row * C_DIM + tid * 4;
#pragma unroll
    for (int u = 0; u < 4; u++) {
        __nv_bfloat16 h16 = __float2bfloat16(y[u]);
        Yh[o + u] = h16; Yl[o + u] = __float2bfloat16(y[u] - __bfloat162float(h16));
    }
}

// ---------------- scalar flash attention (fp32), output bf16 hi/lo ----------------
#define AS 68
#define ATT_SMEM (3 * 64 * AS * 4)
__global__ __launch_bounds__(256) void attn_kernel(
    const float* __restrict__ Q, const float* __restrict__ KV,
    __nv_bfloat16* __restrict__ Oh, __nv_bfloat16* __restrict__ Ol)
{
    extern __shared__ float sm[];
    float* QsT = sm;
    float* KsT = sm + 64 * AS;
    float* Vs  = KsT + 64 * AS;

    int tid = threadIdx.x;
    int b = blockIdx.z, h = blockIdx.y, l0 = blockIdx.x * 64;
    int ty = tid >> 4, tx = tid & 15;

#pragma unroll
    for (int it = 0; it < 4; it++) {
        int row = (tid >> 4) + it * 16, col4 = (tid & 15) * 4;
        float4 v = *(const float4*)&Q[(((size_t)b * L_DIM) + l0 + row) * C_DIM + h * HD + col4];
        QsT[(col4 + 0) * AS + row] = v.x; QsT[(col4 + 1) * AS + row] = v.y;
        QsT[(col4 + 2) * AS + row] = v.z; QsT[(col4 + 3) * AS + row] = v.w;
    }

    float acc[4][4] = {};
    float mrow[4] = {-1e30f, -1e30f, -1e30f, -1e30f};
    float lrow[4] = {};
    const float scale = 0.125f;

    for (int kt = 0; kt < 36; kt++) {
        int kbase = kt * 64;
        __syncthreads();
#pragma unroll
        for (int it = 0; it < 4; it++) {
            int row = (tid >> 4) + it * 16, col4 = (tid & 15) * 4;
            int kg = kbase + row;
            float4 kv4 = make_float4(0.f, 0.f, 0.f, 0.f), vv4 = kv4;
            if (kg < NTOK) {
                size_t base = (((size_t)b * NTOK) + kg) * (size_t)(2 * C_DIM) + h * HD + col4;
                kv4 = *(const float4*)&KV[base];
                vv4 = *(const float4*)&KV[base + C_DIM];
            }
            KsT[(col4 + 0) * AS + row] = kv4.x; KsT[(col4 + 1) * AS + row] = kv4.y;
            KsT[(col4 + 2) * AS + row] = kv4.z; KsT[(col4 + 3) * AS + row] = kv4.w;
            *(float4*)&Vs[row * AS + col4] = vv4;
        }
        __syncthreads();

        float s[4][4] = {};
#pragma unroll 8
        for (int d = 0; d < 64; d++) {
            float4 qv = *(const float4*)&QsT[d * AS + (ty << 2)];
            float4 kb = *(const float4*)&KsT[d * AS + (tx << 2)];
            s[0][0] += qv.x * kb.x; s[0][1] += qv.x * kb.y; s[0][2] += qv.x * kb.z; s[0][3] += qv.x * kb.w;
            s[1][0] += qv.y * kb.x; s[1][1] += qv.y * kb.y; s[1][2] += qv.y * kb.z; s[1][3] += qv.y * kb.w;
            s[2][0] += qv.z * kb.x; s[2][1] += qv.z * kb.y; s[2][2] += qv.z * kb.z; s[2][3] += qv.z * kb.w;
            s[3][0] += qv.w * kb.x; s[3][1] += qv.w * kb.y; s[3][2] += qv.w * kb.z; s[3][3] += qv.w * kb.w;
        }

        float tmax[4];
#pragma unroll
        for (int i = 0; i < 4; i++) {
            tmax[i] = -1e30f;
#pragma unroll
            for (int j = 0; j < 4; j++) {
                int cg = kbase + (tx << 2) + j;
                s[i][j] = (cg < NTOK) ? s[i][j] * scale : -1e30f;
                tmax[i] = fmaxf(tmax[i], s[i][j]);
            }
        }
#pragma unroll
        for (int i = 0; i < 4; i++)
#pragma unroll
            for (int o = 8; o >= 1; o >>= 1)
                tmax[i] = fmaxf(tmax[i], __shfl_xor_sync(0xffffffffu, tmax[i], o));
        float rsum[4];
#pragma unroll
        for (int i = 0; i < 4; i++) {
            float mnew = fmaxf(mrow[i], tmax[i]);
            float alpha = __expf(mrow[i] - mnew);
            mrow[i] = mnew;
            float rs = 0.f;
#pragma unroll
            for (int j = 0; j < 4; j++) {
                float p = (s[i][j] > -1e29f) ? __expf(s[i][j] - mnew) : 0.f;
                s[i][j] = p; rs += p;
            }
            rsum[i] = rs; lrow[i] *= alpha;
#pragma unroll
            for (int j = 0; j < 4; j++) acc[i][j] *= alpha;
        }
#pragma unroll
        for (int i = 0; i < 4; i++) {
#pragma unroll
            for (int o = 8; o >= 1; o >>= 1)
                rsum[i] += __shfl_xor_sync(0xffffffffu, rsum[i], o);
            lrow[i] += rsum[i];
        }

        __syncthreads();
#pragma unroll
        for (int i = 0; i < 4; i++)
#pragma unroll
            for (int j = 0; j < 4; j++)
                KsT[((tx << 2) + j) * AS + (ty << 2) + i] = s[i][j];
        __syncthreads();

#pragma unroll 8
        for (int c = 0; c < 64; c++) {
            float4 pv = *(const float4*)&KsT[c * AS + (ty << 2)];
            float4 v4 = *(const float4*)&Vs[c * AS + (tx << 2)];
            acc[0][0] += pv.x * v4.x; acc[0][1] += pv.x * v4.y; acc[0][2] += pv.x * v4.z; acc[0][3] += pv.x * v4.w;
            acc[1][0] += pv.y * v4.x; acc[1][1] += pv.y * v4.y; acc[1][2] += pv.y * v4.z; acc[1][3] += pv.y * v4.w;
            acc[2][0] += pv.z * v4.x; acc[2][1] += pv.z * v4.y; acc[2][2] += pv.z * v4.z; acc[2][3] += pv.z * v4.w;
            acc[3][0] += pv.w * v4.x; acc[3][1] += pv.w * v4.y; acc[3][2] += pv.w * v4.z; acc[3][3] += pv.w * v4.w;
        }
    }

#pragma unroll
    for (int i = 0; i < 4; i++) {
        float inv = 1.f / lrow[i];
        int row = l0 + (ty << 2) + i;
        size_t o = (((size_t)b * L_DIM) + row) * C_DIM + h * HD + (tx << 2);
#pragma unroll
        for (int j = 0; j < 4; j++) {
            float v = acc[i][j] * inv;
            __nv_bfloat16 h16 = __float2bfloat16(v);
            Oh[o + j] = h16; Ol[o + j] = __float2bfloat16(v - __bfloat162float(h16));
        }
    }
}

// ---------------- launch ----------------
extern "C" void kernel_launch(void* const* d_in, const int* in_sizes, int n_in,
                              void* d_out, int out_size)
{
    const float* x    = (const float*)d_in[0];
    const float* m    = (const float*)d_in[1];
    const float* wsrc5[5] = { (const float*)d_in[2], (const float*)d_in[4], (const float*)d_in[6],
                              (const float*)d_in[8], (const float*)d_in[10] };
    const float* bsrc5[5] = { (const float*)d_in[3], (const float*)d_in[5], (const float*)d_in[7],
                              (const float*)d_in[9], (const float*)d_in[11] };
    const float* ln_g = (const float*)d_in[12];
    const float* ln_b = (const float*)d_in[13];
    const float* Wq   = (const float*)d_in[14];
    const float* Wkv  = (const float*)d_in[15];
    const float* Wp   = (const float*)d_in[16];
    const float* bp   = (const float*)d_in[17];
    float* out  = (float*)d_out;
    float* out2 = (float*)d_out + (size_t)B_DIM * L_DIM * C_DIM;

    float *P0, *P1, *Qb, *KVb;
    __nv_bfloat16 *P0h, *P0l, *P2h, *P2l, *mh, *ml, *Oh, *Ol, *Wth, *Wtl;
    cudaGetSymbolAddress((void**)&P0,  g_P0);
    cudaGetSymbolAddress((void**)&P1,  g_P1);
    cudaGetSymbolAddress((void**)&Qb,  g_Q);
    cudaGetSymbolAddress((void**)&KVb, g_KV);
    cudaGetSymbolAddress((void**)&P0h, g_P0h);
    cudaGetSymbolAddress((void**)&P0l, g_P0l);
    cudaGetSymbolAddress((void**)&P2h, g_P2h);
    cudaGetSymbolAddress((void**)&P2l, g_P2l);
    cudaGetSymbolAddress((void**)&mh,  g_mh);
    cudaGetSymbolAddress((void**)&ml,  g_ml);
    cudaGetSymbolAddress((void**)&Oh,  g_Oh);
    cudaGetSymbolAddress((void**)&Ol,  g_Ol);
    cudaGetSymbolAddress((void**)&Wth, g_Wth);
    cudaGetSymbolAddress((void**)&Wtl, g_Wtl);

    cudaFuncSetAttribute(tgemm_kernel, cudaFuncAttributeMaxDynamicSharedMemorySize, TG_SMEM);
    cudaFuncSetAttribute(attn_kernel,  cudaFuncAttributeMaxDynamicSharedMemorySize, ATT_SMEM);

    // weights -> transposed bf16 hi/lo  (slots: 0-4 conv, 5 Wq, 6 Wp, 7 Wkv)
    const float* wsrc[8] = { wsrc5[0], wsrc5[1], wsrc5[2], wsrc5[3], wsrc5[4], Wq, Wp, Wkv };
    for (int i = 0; i < 8; i++) {
        int N = (i == 7) ? 1024 : 512;
        wsplit_kernel<<<dim3(N / 32, 16), dim3(32, 8)>>>(wsrc[i], Wth + i * WSLOT, Wtl + i * WSLOT, N);
    }
    mcvt_kernel<<<(B_DIM * L_DIM * C_DIM + 255) / 256, 256>>>(m, mh, ml);

    pool_avg_kernel<<<dim3(987, B_DIM), 512>>>(x, P0, P0h, P0l);
    pool_max_kernel<<<dim3(256, B_DIM), 512>>>(x, P0, P0h, P0l);

    const int npix[5] = { 441, 256, 169, 121, 256 };
    const int toff[5] = { 0, 441, 697, 866, OFF_MX };
    for (int i = 0; i < 5; i++) {
        int M = B_DIM * npix[i];
        tgemm_kernel<<<dim3(4, (M + 127) / 128), 256, TG_SMEM>>>(
            P0h, P0l, nullptr, nullptr, Wth + i * WSLOT, Wtl + i * WSLOT,
            bsrc5[i], P0, P1, M, 512, 1, npix[i], toff[i]);
    }

    mx_copy_kernel<<<(B_DIM * C_DIM * 256 + 255) / 256, 256>>>(P1, out2);
    ln_kernel<<<B_DIM * NP, 128>>>(P1, ln_g, ln_b, P2h, P2l);

    // q = m @ Wq
    tgemm_kernel<<<dim3(4, 64), 256, TG_SMEM>>>(
        mh, ml, nullptr, nullptr, Wth + 5 * WSLOT, Wtl + 5 * WSLOT,
        nullptr, nullptr, Qb, B_DIM * L_DIM, 512, 0, 0, 0);

    // kv = [p; m] @ Wkv
    tgemm_kernel<<<dim3(8, (B_DIM * NTOK + 127) / 128), 256, TG_SMEM>>>(
        P2h, P2l, mh, ml, Wth + 7 * WSLOT, Wtl + 7 * WSLOT,
        nullptr, nullptr, KVb, B_DIM * NTOK, 1024, 2, 0, 0);

    // attention
    attn_kernel<<<dim3(L_DIM / 64, NH, B_DIM), 256, ATT_SMEM>>>(Qb, KVb, Oh, Ol);

    // out = O @ Wp + bp
    tgemm_kernel<<<dim3(4, 64), 256, TG_SMEM>>>(
        Oh, Ol, nullptr, nullptr, Wth + 6 * WSLOT, Wtl + 6 * WSLOT,
        bp, nullptr, out, B_DIM * L_DIM, 512, 0, 0, 0);
}

// round 5
// speedup vs baseline: 1.6210x; 1.3028x over previous
#include <cuda_runtime.h>
#include <cuda_bf16.h>
#include <mma.h>
#include <math.h>
#include <cstdint>

using namespace nvcuda;

#define B_DIM 8
#define L_DIM 1024
#define C_DIM 512
#define NP    1243
#define NTOK  2267
#define NH    8
#define HD    64
#define LN_EPS 1e-5f
#define OFF_MX 987

// ---------------- scratch ----------------
__device__ __align__(128) float g_P0[B_DIM * NP * C_DIM];
__device__ __align__(128) float g_P1[B_DIM * NP * C_DIM];
__device__ __align__(128) __nv_bfloat16 g_P0h[B_DIM * NP * C_DIM],    g_P0l[B_DIM * NP * C_DIM];
__device__ __align__(128) __nv_bfloat16 g_P2h[B_DIM * NP * C_DIM],    g_P2l[B_DIM * NP * C_DIM];
__device__ __align__(128) __nv_bfloat16 g_mh [B_DIM * L_DIM * C_DIM], g_ml [B_DIM * L_DIM * C_DIM];
__device__ __align__(128) __nv_bfloat16 g_Qh [B_DIM * L_DIM * C_DIM], g_Ql [B_DIM * L_DIM * C_DIM];
__device__ __align__(128) __nv_bfloat16 g_KVh[B_DIM * NTOK * 2 * C_DIM], g_KVl[B_DIM * NTOK * 2 * C_DIM];
__device__ __align__(128) __nv_bfloat16 g_Oh [B_DIM * L_DIM * C_DIM], g_Ol [B_DIM * L_DIM * C_DIM];
#define WSLOT (512 * 512)
__device__ __align__(128) __nv_bfloat16 g_Wth[7 * WSLOT + 512 * 1024], g_Wtl[7 * WSLOT + 512 * 1024];

// ---------------- helpers ----------------
__device__ __forceinline__ uint32_t smem_u32(const void* p) {
    uint32_t a;
    asm("{ .reg .u64 t; cvta.to.shared.u64 t, %1; cvt.u32.u64 %0, t; }" : "=r"(a) : "l"(p));
    return a;
}
__device__ __forceinline__ void cp16(uint32_t dst, const void* src) {
    asm volatile("cp.async.cg.shared.global [%0], [%1], 16;" :: "r"(dst), "l"(src) : "memory");
}
__device__ __forceinline__ void cp16z(uint32_t dst, const void* src, int sz) {
    asm volatile("cp.async.cg.shared.global [%0], [%1], 16, %2;" :: "r"(dst), "l"(src), "r"(sz) : "memory");
}
#define CP_COMMIT() asm volatile("cp.async.commit_group;" ::: "memory")
#define CP_WAIT1()  asm volatile("cp.async.wait_group 1;" ::: "memory")
#define CP_WAIT0()  asm volatile("cp.async.wait_group 0;" ::: "memory")

// ---------------- combined weight transpose + split ----------------
// 8 weight slots; slot 7 (Wkv) has N=1024, others 512. T[N][512] hi/lo.
__global__ void wsplit8_kernel(const float* W0, const float* W1, const float* W2, const float* W3,
                               const float* W4, const float* W5, const float* W6, const float* W7,
                               __nv_bfloat16* __restrict__ Th, __nv_bfloat16* __restrict__ Tl)
{
    __shared__ float t[32][33];
    int slot = blockIdx.z;
    const float* W = (slot == 0) ? W0 : (slot == 1) ? W1 : (slot == 2) ? W2 : (slot == 3) ? W3 :
                     (slot == 4) ? W4 : (slot == 5) ? W5 : (slot == 6) ? W6 : W7;
    int N = (slot == 7) ? 1024 : 512;
    int n0 = blockIdx.x * 32, k0 = blockIdx.y * 32;
    if (n0 >= N) return;
    __nv_bfloat16* th = Th + (size_t)slot * WSLOT;
    __nv_bfloat16* tl = Tl + (size_t)slot * WSLOT;
    int tx = threadIdx.x, ty = threadIdx.y;
    for (int i = ty; i < 32; i += 8) t[i][tx] = W[(size_t)(k0 + i) * N + n0 + tx];
    __syncthreads();
    for (int i = ty; i < 32; i += 8) {
        float v = t[tx][i];
        __nv_bfloat16 h = __float2bfloat16(v);
        size_t o = (size_t)(n0 + i) * 512 + k0 + tx;
        th[o] = h; tl[o] = __float2bfloat16(v - __bfloat162float(h));
    }
}

__global__ void mcvt_kernel(const float* __restrict__ m, __nv_bfloat16* __restrict__ mh,
                            __nv_bfloat16* __restrict__ ml)
{
    int i = blockIdx.x * blockDim.x + threadIdx.x;
    if (i >= B_DIM * L_DIM * C_DIM) return;
    float v = m[i];
    __nv_bfloat16 h = __float2bfloat16(v);
    mh[i] = h; ml[i] = __float2bfloat16(v - __bfloat162float(h));
}

// ---------------- pooling ----------------
__global__ void pool_avg_kernel(const float* __restrict__ x, float* __restrict__ P0,
                                __nv_bfloat16* __restrict__ Ph, __nv_bfloat16* __restrict__ Pl)
{
    int tok = blockIdx.x, b = blockIdx.y, c = threadIdx.x;
    int t = tok, n;
    if      (t < 441) { n = 21; }
    else if (t < 697) { n = 16; t -= 441; }
    else if (t < 866) { n = 13; t -= 697; }
    else              { n = 11; t -= 866; }
    int p = t / n, q = t - p * n;
    int hs = (p * 64) / n, he = ((p + 1) * 64 + n - 1) / n;
    int ws = (q * 64) / n, we = ((q + 1) * 64 + n - 1) / n;
    float s = 0.f;
    for (int h = hs; h < he; h++) {
        const float* xr = x + (((size_t)b * 4096) + (size_t)h * 64) * C_DIM + c;
        for (int w = ws; w < we; w++) s += xr[(size_t)w * C_DIM];
    }
    float v = s / (float)((he - hs) * (we - ws));
    size_t o = ((size_t)b * NP + tok) * C_DIM + c;
    P0[o] = v;
    __nv_bfloat16 h16 = __float2bfloat16(v);
    Ph[o] = h16; Pl[o] = __float2bfloat16(v - __bfloat162float(h16));
}

__global__ void pool_max_kernel(const float* __restrict__ x, float* __restrict__ P0,
                                __nv_bfloat16* __restrict__ Ph, __nv_bfloat16* __restrict__ Pl)
{
    int t = blockIdx.x, b = blockIdx.y, c = threadIdx.x;
    int p = t >> 4, q = t & 15;
    float mx = -1e30f;
    for (int h = p * 4; h < p * 4 + 4; h++) {
        const float* xr = x + (((size_t)b * 4096) + (size_t)h * 64) * C_DIM + c;
        for (int w = q * 4; w < q * 4 + 4; w++) mx = fmaxf(mx, xr[(size_t)w * C_DIM]);
    }
    size_t o = ((size_t)b * NP + OFF_MX + t) * C_DIM + c;
    P0[o] = mx;
    __nv_bfloat16 h16 = __float2bfloat16(mx);
    Ph[o] = h16; Pl[o] = __float2bfloat16(mx - __bfloat162float(h16));
}

// =====================================================================
// wmma bf16x3 GEMM: 128x128 block tile, K = 512, chunks of 32,
// double-buffered cp.async. 8 warps, warp tile 64(m) x 32(n).
// Epilogue: f32 out (+bias/residual) OR bf16 hi/lo dual output.
// =====================================================================
#define STG0    4096
#define STG_SZ  40960
#define TG_SMEM (4096 + 2 * 40960)
#define CPITCH  136

__global__ __launch_bounds__(256) void tgemm_kernel(
    const __nv_bfloat16* __restrict__ Ah, const __nv_bfloat16* __restrict__ Al,
    const __nv_bfloat16* __restrict__ A2h, const __nv_bfloat16* __restrict__ A2l,
    const __nv_bfloat16* __restrict__ Bh, const __nv_bfloat16* __restrict__ Bl,
    const float* __restrict__ bias, const float* __restrict__ resid,
    float* __restrict__ Cout,
    __nv_bfloat16* __restrict__ outh, __nv_bfloat16* __restrict__ outl,
    int M, int N, int mode, int npix, int tok_off)
{
    extern __shared__ char sm_raw[];
    const __nv_bfloat16** aptrs = (const __nv_bfloat16**)(sm_raw + 16);
    uint32_t sb = smem_u32(sm_raw);

    int tid = threadIdx.x;
    int brow = blockIdx.y * 128, bcol = blockIdx.x * 128;

    if (tid < 128) {
        int arow = brow + tid;
        if (arow >= M) arow = M - 1;
        const __nv_bfloat16 *ph, *pl;
        if (mode == 0) {
            size_t o = (size_t)arow * 512; ph = Ah + o; pl = Al + o;
        } else if (mode == 1) {
            int b = arow / npix, t = arow - (arow / npix) * npix;
            size_t o = ((size_t)b * NP + tok_off + t) * 512; ph = Ah + o; pl = Al + o;
        } else {
            int b = arow / NTOK, t = arow - (arow / NTOK) * NTOK;
            if (t < NP) { size_t o = ((size_t)b * NP + t) * 512; ph = Ah + o; pl = Al + o; }
            else        { size_t o = ((size_t)b * L_DIM + (t - NP)) * 512; ph = A2h + o; pl = A2l + o; }
        }
        aptrs[tid] = ph; aptrs[128 + tid] = pl;
    }
    __syncthreads();

    int wid = tid >> 5;
    int wm = wid & 1, wn = wid >> 1;

    wmma::fragment<wmma::accumulator, 16, 16, 16, float> acc[4][2];
#pragma unroll
    for (int mi = 0; mi < 4; mi++)
#pragma unroll
        for (int ni = 0; ni < 2; ni++)
            wmma::fill_fragment(acc[mi][ni], 0.f);

    {
        uint32_t st = sb + STG0;
#pragma unroll
        for (int w = 0; w < 8; w++) {
            int ci = tid + w * 256;
            int region = ci >> 9, idx = ci & 511;
            int row = idx >> 2, ch = idx & 3;
            const __nv_bfloat16* src;
            if (region < 2) src = aptrs[region * 128 + row] + ch * 8;
            else            src = ((region == 2) ? Bh : Bl) + (size_t)(bcol + row) * 512 + ch * 8;
            cp16(st + region * 10240 + row * 80 + ch * 16, src);
        }
        CP_COMMIT();
    }

    for (int j = 0; j < 16; j++) {
        if (j + 1 < 16) {
            uint32_t st = sb + STG0 + ((j + 1) & 1) * STG_SZ;
            int koff = (j + 1) * 32;
#pragma unroll
            for (int w = 0; w < 8; w++) {
                int ci = tid + w * 256;
                int region = ci >> 9, idx = ci & 511;
                int row = idx >> 2, ch = idx & 3;
                const __nv_bfloat16* src;
                if (region < 2) src = aptrs[region * 128 + row] + koff + ch * 8;
                else            src = ((region == 2) ? Bh : Bl) + (size_t)(bcol + row) * 512 + koff + ch * 8;
                cp16(st + region * 10240 + row * 80 + ch * 16, src);
            }
            CP_COMMIT();
            CP_WAIT1();
        } else {
            CP_WAIT0();
        }
        __syncthreads();

        const __nv_bfloat16* st = (const __nv_bfloat16*)(sm_raw + STG0 + (j & 1) * STG_SZ);
        const __nv_bfloat16* As_h = st;
        const __nv_bfloat16* As_l = st + 5120;
        const __nv_bfloat16* Bs_h = st + 10240;
        const __nv_bfloat16* Bs_l = st + 15360;

#pragma unroll
        for (int kk = 0; kk < 2; kk++) {
            wmma::fragment<wmma::matrix_a, 16, 16, 16, __nv_bfloat16, wmma::row_major> fah[4], fal[4];
            wmma::fragment<wmma::matrix_b, 16, 16, 16, __nv_bfloat16, wmma::col_major> fbh[2], fbl[2];
#pragma unroll
            for (int mi = 0; mi < 4; mi++) {
                int r = wm * 64 + mi * 16;
                wmma::load_matrix_sync(fah[mi], As_h + r * 40 + kk * 16, 40);
                wmma::load_matrix_sync(fal[mi], As_l + r * 40 + kk * 16, 40);
            }
#pragma unroll
            for (int ni = 0; ni < 2; ni++) {
                int c = wn * 32 + ni * 16;
                wmma::load_matrix_sync(fbh[ni], Bs_h + c * 40 + kk * 16, 40);
                wmma::load_matrix_sync(fbl[ni], Bs_l + c * 40 + kk * 16, 40);
            }
#pragma unroll
            for (int mi = 0; mi < 4; mi++)
#pragma unroll
                for (int ni = 0; ni < 2; ni++) {
                    wmma::mma_sync(acc[mi][ni], fah[mi], fbh[ni], acc[mi][ni]);
                    wmma::mma_sync(acc[mi][ni], fah[mi], fbl[ni], acc[mi][ni]);
                    wmma::mma_sync(acc[mi][ni], fal[mi], fbh[ni], acc[mi][ni]);
                }
        }
        __syncthreads();
    }

    float* Cs = (float*)(sm_raw + STG0);
#pragma unroll
    for (int mi = 0; mi < 4; mi++)
#pragma unroll
        for (int ni = 0; ni < 2; ni++)
            wmma::store_matrix_sync(Cs + (wm * 64 + mi * 16) * CPITCH + wn * 32 + ni * 16,
                                    acc[mi][ni], CPITCH, wmma::mem_row_major);
    __syncthreads();

    int lane = tid & 31, wrow = tid >> 5;
    for (int rr = wrow; rr < 128; rr += 8) {
        int r = brow + rr;
        if (r >= M) continue;
        int col0 = lane * 4;
        float4 o = *(float4*)&Cs[rr * CPITCH + col0];
        int col = bcol + col0;
        if (bias) {
            o.x += bias[col];     o.y += bias[col + 1];
            o.z += bias[col + 2]; o.w += bias[col + 3];
        }
        if (mode == 1) {
            int b = r / npix, t = r - (r / npix) * npix;
            size_t g = ((size_t)b * NP + tok_off + t) * 512;
            float4 rv = *(const float4*)&resid[g + col];
            o.x += rv.x; o.y += rv.y; o.z += rv.z; o.w += rv.w;
            *(float4*)&Cout[g + col] = o;
        } else if (outh) {
            size_t g = (size_t)r * N + col;
            float vv[4] = { o.x, o.y, o.z, o.w };
#pragma unroll
            for (int u = 0; u < 4; u++) {
                __nv_bfloat16 h16 = __float2bfloat16(vv[u]);
                outh[g + u] = h16;
                outl[g + u] = __float2bfloat16(vv[u] - __bfloat162float(h16));
            }
        } else {
            *(float4*)&Cout[(size_t)r * N + col] = o;
        }
    }
}

// ---------------- mx copy ----------------
__global__ void mx_copy_kernel(const float* __restrict__ P1, float* __restrict__ out2)
{
    int idx = blockIdx.x * blockDim.x + threadIdx.x;
    if (idx >= B_DIM * C_DIM * 256) return;
    int t = idx & 255, c = (idx >> 8) & 511, b = idx >> 17;
    out2[idx] = P1[(((size_t)b * NP) + OFF_MX + t) * C_DIM + c];
}

// ---------------- layernorm -> bf16 hi/lo ----------------
__global__ void ln_kernel(const float* __restrict__ X, const float* __restrict__ g,
                          const float* __restrict__ be,
                          __nv_bfloat16* __restrict__ Yh, __nv_bfloat16* __restrict__ Yl)
{
    int row = blockIdx.x, tid = threadIdx.x;
    float4 v = ((const float4*)(X + (size_t)row * C_DIM))[tid];
    float s  = v.x + v.y + v.z + v.w;
    float s2 = v.x * v.x + v.y * v.y + v.z * v.z + v.w * v.w;
#pragma unroll
    for (int o = 16; o >= 1; o >>= 1) {
        s  += __shfl_xor_sync(0xffffffffu, s,  o);
        s2 += __shfl_xor_sync(0xffffffffu, s2, o);
    }
    __shared__ float ws[4], ws2[4];
    int wid = tid >> 5, lane = tid & 31;
    if (lane == 0) { ws[wid] = s; ws2[wid] = s2; }
    __syncthreads();
    float ts = ws[0] + ws[1] + ws[2] + ws[3], ts2 = ws2[0] + ws2[1] + ws2[2] + ws2[3];
    float mean = ts * (1.f / C_DIM);
    float var  = ts2 * (1.f / C_DIM) - mean * mean;
    float rstd = rsqrtf(var + LN_EPS);
    float4 gg = ((const float4*)g)[tid], bb = ((const float4*)be)[tid];
    float y[4] = { (v.x - mean) * rstd * gg.x + bb.x, (v.y - mean) * rstd * gg.y + bb.y,
                   (v.z - mean) * rstd * gg.z + bb.z, (v.w - mean) * rstd * gg.w + bb.w };
    size_t o = (size_t)row * C_DIM + tid * 4;
#pragma unroll
    for (int u = 0; u < 4; u++) {
        __nv_bfloat16 h16 = __float2bfloat16(y[u]);
        Yh[o + u] = h16; Yl[o + u] = __float2bfloat16(y[u] - __bfloat162float(h16));
    }
}

// =====================================================================
// wmma flash attention, bf16x3, online softmax with smem O accumulator.
// 256 threads / 8 warps; per block: (b, h, 64-query tile); 36 key tiles.
// =====================================================================
#define QP 72     // bf16 tile pitch (elements)
#define SP 68     // f32 pitch
#define ATT_SMEM (8 * 64 * QP * 2 + 2 * 64 * SP * 4)   // 73728 + 34816 = 108544

__global__ __launch_bounds__(256) void attn_wmma_kernel(
    const __nv_bfloat16* __restrict__ Qh, const __nv_bfloat16* __restrict__ Ql,
    const __nv_bfloat16* __restrict__ KVh, const __nv_bfloat16* __restrict__ KVl,
    __nv_bfloat16* __restrict__ Oh, __nv_bfloat16* __restrict__ Ol)
{
    extern __shared__ char smc[];
    __nv_bfloat16* sQh = (__nv_bfloat16*)smc;
    __nv_bfloat16* sQl = sQh + 64 * QP;
    __nv_bfloat16* sKh = sQl + 64 * QP;
    __nv_bfloat16* sKl = sKh + 64 * QP;
    __nv_bfloat16* sVh = sKl + 64 * QP;
    __nv_bfloat16* sVl = sVh + 64 * QP;
    __nv_bfloat16* sPh = sVl + 64 * QP;
    __nv_bfloat16* sPl = sPh + 64 * QP;
    float* Ss = (float*)(sPl + 64 * QP);   // [64][68]
    float* Oa = Ss + 64 * SP;              // [64][68]

    int tid = threadIdx.x;
    int b = blockIdx.z, h = blockIdx.y, l0 = blockIdx.x * 64;
    int warp = tid >> 5;
    int wm = (warp & 1) * 32, wn = (warp >> 1) * 16;
    int ty = tid >> 4, tx = tid & 15;
    const float scale = 0.125f;

    // async-load Q hi/lo (64x64 bf16 each)
#pragma unroll
    for (int w = 0; w < 4; w++) {
        int ci = tid + w * 256;              // 0..1023
        int arr = ci >> 9, idx = ci & 511;
        int row = idx >> 3, ch = idx & 7;
        const __nv_bfloat16* src = (arr ? Ql : Qh) +
            (((size_t)b * L_DIM) + l0 + row) * 512 + h * 64 + ch * 8;
        cp16(smem_u32((arr ? sQl : sQh) + row * QP + ch * 8), src);
    }
    CP_COMMIT();

    for (int i = tid; i < 64 * SP; i += 256) Oa[i] = 0.f;
    float mrow[4] = { -1e30f, -1e30f, -1e30f, -1e30f };
    float lrow[4] = {};

    for (int kt = 0; kt < 36; kt++) {
        int kbase = kt * 64;
        // async-load K/V hi/lo tiles (zfill beyond NTOK)
#pragma unroll
        for (int w = 0; w < 8; w++) {
            int ci = tid + w * 256;          // 0..2047
            int arr = ci >> 9, idx = ci & 511;
            int row = idx >> 3, ch = idx & 7;
            int kg = kbase + row;
            const __nv_bfloat16* gb = (arr & 1) ? KVl : KVh;
            size_t off = (((size_t)b * NTOK) + (kg < NTOK ? kg : 0)) * 1024
                       + (arr >> 1) * 512 + h * 64 + ch * 8;
            __nv_bfloat16* dstb = (arr == 0) ? sKh : (arr == 1) ? sKl : (arr == 2) ? sVh : sVl;
            cp16z(smem_u32(dstb + row * QP + ch * 8), gb + off, (kg < NTOK) ? 16 : 0);
        }
        CP_COMMIT();
        CP_WAIT0();
        __syncthreads();

        // ---- S = Q K^T (bf16x3) ----
        {
            wmma::fragment<wmma::accumulator, 16, 16, 16, float> sf[2];
            wmma::fill_fragment(sf[0], 0.f);
            wmma::fill_fragment(sf[1], 0.f);
#pragma unroll
            for (int k = 0; k < 4; k++) {
                wmma::fragment<wmma::matrix_b, 16, 16, 16, __nv_bfloat16, wmma::col_major> fbh, fbl;
                wmma::load_matrix_sync(fbh, sKh + wn * QP + k * 16, QP);
                wmma::load_matrix_sync(fbl, sKl + wn * QP + k * 16, QP);
#pragma unroll
                for (int mi = 0; mi < 2; mi++) {
                    wmma::fragment<wmma::matrix_a, 16, 16, 16, __nv_bfloat16, wmma::row_major> fah, fal;
                    wmma::load_matrix_sync(fah, sQh + (wm + mi * 16) * QP + k * 16, QP);
                    wmma::load_matrix_sync(fal, sQl + (wm + mi * 16) * QP + k * 16, QP);
                    wmma::mma_sync(sf[mi], fah, fbh, sf[mi]);
                    wmma::mma_sync(sf[mi], fah, fbl, sf[mi]);
                    wmma::mma_sync(sf[mi], fal, fbh, sf[mi]);
                }
            }
            wmma::store_matrix_sync(Ss + wm * SP + wn, sf[0], SP, wmma::mem_row_major);
            wmma::store_matrix_sync(Ss + (wm + 16) * SP + wn, sf[1], SP, wmma::mem_row_major);
        }
        __syncthreads();

        // ---- scalar online softmax on 4x4 patch ----
        float s[4][4], tmax[4];
#pragma unroll
        for (int i = 0; i < 4; i++) {
            float4 sv = *(const float4*)&Ss[(ty * 4 + i) * SP + tx * 4];
            s[i][0] = sv.x; s[i][1] = sv.y; s[i][2] = sv.z; s[i][3] = sv.w;
            tmax[i] = -1e30f;
#pragma unroll
            for (int j = 0; j < 4; j++) {
                int cg = kbase + tx * 4 + j;
                s[i][j] = (cg < NTOK) ? s[i][j] * scale : -1e30f;
                tmax[i] = fmaxf(tmax[i], s[i][j]);
            }
        }
#pragma unroll
        for (int i = 0; i < 4; i++)
#pragma unroll
            for (int o = 8; o >= 1; o >>= 1)
                tmax[i] = fmaxf(tmax[i], __shfl_xor_sync(0xffffffffu, tmax[i], o));
        float alpha[4], rsum[4];
#pragma unroll
        for (int i = 0; i < 4; i++) {
            float mnew = fmaxf(mrow[i], tmax[i]);
            alpha[i] = __expf(mrow[i] - mnew);
            mrow[i] = mnew;
            float rs = 0.f;
#pragma unroll
            for (int j = 0; j < 4; j++) {
                float p = (s[i][j] > -1e29f) ? __expf(s[i][j] - mnew) : 0.f;
                s[i][j] = p; rs += p;
            }
            rsum[i] = rs;
            lrow[i] = lrow[i] * alpha[i];
        }
#pragma unroll
        for (int i = 0; i < 4; i++) {
#pragma unroll
            for (int o = 8; o >= 1; o >>= 1)
                rsum[i] += __shfl_xor_sync(0xffffffffu, rsum[i], o);
            lrow[i] += rsum[i];
        }
        // write P hi/lo, rescale O accumulator
#pragma unroll
        for (int i = 0; i < 4; i++) {
            int r = ty * 4 + i;
#pragma unroll
            for (int j = 0; j < 4; j++) {
                float p = s[i][j];
                __nv_bfloat16 h16 = __float2bfloat16(p);
                sPh[r * QP + tx * 4 + j] = h16;
                sPl[r * QP + tx * 4 + j] = __float2bfloat16(p - __bfloat162float(h16));
            }
            float4 ov = *(float4*)&Oa[r * SP + tx * 4];
            ov.x *= alpha[i]; ov.y *= alpha[i]; ov.z *= alpha[i]; ov.w *= alpha[i];
            *(float4*)&Oa[r * SP + tx * 4] = ov;
        }
        __syncthreads();

        // ---- O_tile = P V (bf16x3) ----
        {
            wmma::fragment<wmma::accumulator, 16, 16, 16, float> of[2];
            wmma::fill_fragment(of[0], 0.f);
            wmma::fill_fragment(of[1], 0.f);
#pragma unroll
            for (int k = 0; k < 4; k++) {
                wmma::fragment<wmma::matrix_b, 16, 16, 16, __nv_bfloat16, wmma::row_major> fbh, fbl;
                wmma::load_matrix_sync(fbh, sVh + k * 16 * QP + wn, QP);
                wmma::load_matrix_sync(fbl, sVl + k * 16 * QP + wn, QP);
#pragma unroll
                for (int mi = 0; mi < 2; mi++) {
                    wmma::fragment<wmma::matrix_a, 16, 16, 16, __nv_bfloat16, wmma::row_major> fah, fal;
                    wmma::load_matrix_sync(fah, sPh + (wm + mi * 16) * QP + k * 16, QP);
                    wmma::load_matrix_sync(fal, sPl + (wm + mi * 16) * QP + k * 16, QP);
                    wmma::mma_sync(of[mi], fah, fbh, of[mi]);
                    wmma::mma_sync(of[mi], fah, fbl, of[mi]);
                    wmma::mma_sync(of[mi], fal, fbh, of[mi]);
                }
            }
            wmma::store_matrix_sync(Ss + wm * SP + wn, of[0], SP, wmma::mem_row_major);
            wmma::store_matrix_sync(Ss + (wm + 16) * SP + wn, of[1], SP, wmma::mem_row_major);
        }
        __syncthreads();

        // accumulate
#pragma unroll
        for (int i = 0; i < 4; i++) {
            int r = ty * 4 + i;
            float4 ov = *(float4*)&Oa[r * SP + tx * 4];
            float4 tv = *(const float4*)&Ss[r * SP + tx * 4];
            ov.x += tv.x; ov.y += tv.y; ov.z += tv.z; ov.w += tv.w;
            *(float4*)&Oa[r * SP + tx * 4] = ov;
        }
        __syncthreads();
    }

    // normalize + store bf16 hi/lo
#pragma unroll
    for (int i = 0; i < 4; i++) {
        float inv = 1.f / lrow[i];
        int r = ty * 4 + i;
        size_t o = (((size_t)b * L_DIM) + l0 + r) * C_DIM + h * HD + tx * 4;
#pragma unroll
        for (int j = 0; j < 4; j++) {
            float v = Oa[r * SP + tx * 4 + j] * inv;
            __nv_bfloat16 h16 = __float2bfloat16(v);
            Oh[o + j] = h16; Ol[o + j] = __float2bfloat16(v - __bfloat162float(h16));
        }
    }
}

// ---------------- launch ----------------
extern "C" void kernel_launch(void* const* d_in, const int* in_sizes, int n_in,
                              void* d_out, int out_size)
{
    const float* x    = (const float*)d_in[0];
    const float* m    = (const float*)d_in[1];
    const float* wsrc5[5] = { (const float*)d_in[2], (const float*)d_in[4], (const float*)d_in[6],
                              (const float*)d_in[8], (const float*)d_in[10] };
    const float* bsrc5[5] = { (const float*)d_in[3], (const float*)d_in[5], (const float*)d_in[7],
                              (const float*)d_in[9], (const float*)d_in[11] };
    const float* ln_g = (const float*)d_in[12];
    const float* ln_b = (const float*)d_in[13];
    const float* Wq   = (const float*)d_in[14];
    const float* Wkv  = (const float*)d_in[15];
    const float* Wp   = (const float*)d_in[16];
    const float* bp   = (const float*)d_in[17];
    float* out  = (float*)d_out;
    float* out2 = (float*)d_out + (size_t)B_DIM * L_DIM * C_DIM;

    float *P0, *P1;
    __nv_bfloat16 *P0h, *P0l, *P2h, *P2l, *mh, *ml, *Qh, *Ql, *KVh, *KVl, *Oh, *Ol, *Wth, *Wtl;
    cudaGetSymbolAddress((void**)&P0,  g_P0);
    cudaGetSymbolAddress((void**)&P1,  g_P1);
    cudaGetSymbolAddress((void**)&P0h, g_P0h);
    cudaGetSymbolAddress((void**)&P0l, g_P0l);
    cudaGetSymbolAddress((void**)&P2h, g_P2h);
    cudaGetSymbolAddress((void**)&P2l, g_P2l);
    cudaGetSymbolAddress((void**)&mh,  g_mh);
    cudaGetSymbolAddress((void**)&ml,  g_ml);
    cudaGetSymbolAddress((void**)&Qh,  g_Qh);
    cudaGetSymbolAddress((void**)&Ql,  g_Ql);
    cudaGetSymbolAddress((void**)&KVh, g_KVh);
    cudaGetSymbolAddress((void**)&KVl, g_KVl);
    cudaGetSymbolAddress((void**)&Oh,  g_Oh);
    cudaGetSymbolAddress((void**)&Ol,  g_Ol);
    cudaGetSymbolAddress((void**)&Wth, g_Wth);
    cudaGetSymbolAddress((void**)&Wtl, g_Wtl);

    cudaFuncSetAttribute(tgemm_kernel,     cudaFuncAttributeMaxDynamicSharedMemorySize, TG_SMEM);
    cudaFuncSetAttribute(attn_wmma_kernel, cudaFuncAttributeMaxDynamicSharedMemorySize, ATT_SMEM);

    wsplit8_kernel<<<dim3(32, 16, 8), dim3(32, 8)>>>(
        wsrc5[0], wsrc5[1], wsrc5[2], wsrc5[3], wsrc5[4], Wq, Wp, Wkv, Wth, Wtl);
    mcvt_kernel<<<(B_DIM * L_DIM * C_DIM + 255) / 256, 256>>>(m, mh, ml);

    pool_avg_kernel<<<dim3(987, B_DIM), 512>>>(x, P0, P0h, P0l);
    pool_max_kernel<<<dim3(256, B_DIM), 512>>>(x, P0, P0h, P0l);

    const int npix[5] = { 441, 256, 169, 121, 256 };
    const int toff[5] = { 0, 441, 697, 866, OFF_MX };
    for (int i = 0; i < 5; i++) {
        int M = B_DIM * npix[i];
        tgemm_kernel<<<dim3(4, (M + 127) / 128), 256, TG_SMEM>>>(
            P0h, P0l, nullptr, nullptr, Wth + (size_t)i * WSLOT, Wtl + (size_t)i * WSLOT,
            bsrc5[i], P0, P1, nullptr, nullptr, M, 512, 1, npix[i], toff[i]);
    }

    mx_copy_kernel<<<(B_DIM * C_DIM * 256 + 255) / 256, 256>>>(P1, out2);
    ln_kernel<<<B_DIM * NP, 128>>>(P1, ln_g, ln_b, P2h, P2l);

    // q = m @ Wq  -> bf16 hi/lo
    tgemm_kernel<<<dim3(4, 64), 256, TG_SMEM>>>(
        mh, ml, nullptr, nullptr, Wth + 5 * (size_t)WSLOT, Wtl + 5 * (size_t)WSLOT,
        nullptr, nullptr, nullptr, Qh, Ql, B_DIM * L_DIM, 512, 0, 0, 0);

    // kv = [p; m] @ Wkv  -> bf16 hi/lo
    tgemm_kernel<<<dim3(8, (B_DIM * NTOK + 127) / 128), 256, TG_SMEM>>>(
        P2h, P2l, mh, ml, Wth + 7 * (size_t)WSLOT, Wtl + 7 * (size_t)WSLOT,
        nullptr, nullptr, nullptr, KVh, KVl, B_DIM * NTOK, 1024, 2, 0, 0);

    // attention (wmma)
    attn_wmma_kernel<<<dim3(L_DIM / 64, NH, B_DIM), 256, ATT_SMEM>>>(Qh, Ql, KVh, KVl, Oh, Ol);

    // out = O @ Wp + bp (f32)
    tgemm_kernel<<<dim3(4, 64), 256, TG_SMEM>>>(
        Oh, Ol, nullptr, nullptr, Wth + 6 * (size_t)WSLOT, Wtl + 6 * (size_t)WSLOT,
        bp, nullptr, out, nullptr, nullptr, B_DIM * L_DIM, 512, 0, 0, 0);
}

// round 6
// speedup vs baseline: 1.8549x; 1.1443x over previous
#include <cuda_runtime.h>
#include <cuda_bf16.h>
#include <mma.h>
#include <math.h>
#include <cstdint>

using namespace nvcuda;

#define B_DIM 8
#define L_DIM 1024
#define C_DIM 512
#define NP    1243
#define NTOK  2267
#define NH    8
#define HD    64
#define LN_EPS 1e-5f
#define OFF_MX 987

// ---------------- scratch ----------------
__device__ __align__(128) float g_P0[B_DIM * NP * C_DIM];
__device__ __align__(128) float g_P1[B_DIM * NP * C_DIM];
__device__ __align__(128) __nv_bfloat16 g_P0h[B_DIM * NP * C_DIM],    g_P0l[B_DIM * NP * C_DIM];
__device__ __align__(128) __nv_bfloat16 g_P2h[B_DIM * NP * C_DIM],    g_P2l[B_DIM * NP * C_DIM];
__device__ __align__(128) __nv_bfloat16 g_mh [B_DIM * L_DIM * C_DIM], g_ml [B_DIM * L_DIM * C_DIM];
__device__ __align__(128) __nv_bfloat16 g_Qh [B_DIM * L_DIM * C_DIM], g_Ql [B_DIM * L_DIM * C_DIM];
__device__ __align__(128) __nv_bfloat16 g_KVh[B_DIM * NTOK * 2 * C_DIM], g_KVl[B_DIM * NTOK * 2 * C_DIM];
__device__ __align__(128) __nv_bfloat16 g_Oh [B_DIM * L_DIM * C_DIM], g_Ol [B_DIM * L_DIM * C_DIM];
#define WSLOT (512 * 512)
__device__ __align__(128) __nv_bfloat16 g_Wth[7 * WSLOT + 512 * 1024], g_Wtl[7 * WSLOT + 512 * 1024];

// ---------------- helpers ----------------
__device__ __forceinline__ uint32_t smem_u32(const void* p) {
    uint32_t a;
    asm("{ .reg .u64 t; cvta.to.shared.u64 t, %1; cvt.u32.u64 %0, t; }" : "=r"(a) : "l"(p));
    return a;
}
__device__ __forceinline__ void cp16(uint32_t dst, const void* src) {
    asm volatile("cp.async.cg.shared.global [%0], [%1], 16;" :: "r"(dst), "l"(src) : "memory");
}
__device__ __forceinline__ void cp16z(uint32_t dst, const void* src, int sz) {
    asm volatile("cp.async.cg.shared.global [%0], [%1], 16, %2;" :: "r"(dst), "l"(src), "r"(sz) : "memory");
}
#define CP_COMMIT() asm volatile("cp.async.commit_group;" ::: "memory")
#define CP_WAIT1()  asm volatile("cp.async.wait_group 1;" ::: "memory")
#define CP_WAIT0()  asm volatile("cp.async.wait_group 0;" ::: "memory")

__device__ __forceinline__ uint32_t pk2(float a, float b) {
    __nv_bfloat162 t(__float2bfloat16(a), __float2bfloat16(b));
    return *(uint32_t*)&t;
}
// pack 4 floats into hi uint2 + lo uint2 (bf16x3 split)
__device__ __forceinline__ void split4(const float* v, uint2& hi, uint2& lo) {
    __nv_bfloat16 h[4]; float r[4];
#pragma unroll
    for (int u = 0; u < 4; u++) { h[u] = __float2bfloat16(v[u]); r[u] = v[u] - __bfloat162float(h[u]); }
    __nv_bfloat162 h01(h[0], h[1]), h23(h[2], h[3]);
    hi.x = *(uint32_t*)&h01; hi.y = *(uint32_t*)&h23;
    lo.x = pk2(r[0], r[1]);  lo.y = pk2(r[2], r[3]);
}

// ---------------- combined weight transpose + split ----------------
__global__ void wsplit8_kernel(const float* W0, const float* W1, const float* W2, const float* W3,
                               const float* W4, const float* W5, const float* W6, const float* W7,
                               __nv_bfloat16* __restrict__ Th, __nv_bfloat16* __restrict__ Tl)
{
    __shared__ float t[32][33];
    int slot = blockIdx.z;
    const float* W = (slot == 0) ? W0 : (slot == 1) ? W1 : (slot == 2) ? W2 : (slot == 3) ? W3 :
                     (slot == 4) ? W4 : (slot == 5) ? W5 : (slot == 6) ? W6 : W7;
    int N = (slot == 7) ? 1024 : 512;
    int n0 = blockIdx.x * 32, k0 = blockIdx.y * 32;
    if (n0 >= N) return;
    __nv_bfloat16* th = Th + (size_t)slot * WSLOT;
    __nv_bfloat16* tl = Tl + (size_t)slot * WSLOT;
    int tx = threadIdx.x, ty = threadIdx.y;
    for (int i = ty; i < 32; i += 8) t[i][tx] = W[(size_t)(k0 + i) * N + n0 + tx];
    __syncthreads();
    for (int i = ty; i < 32; i += 8) {
        float v = t[tx][i];
        __nv_bfloat16 h = __float2bfloat16(v);
        size_t o = (size_t)(n0 + i) * 512 + k0 + tx;
        th[o] = h; tl[o] = __float2bfloat16(v - __bfloat162float(h));
    }
}

__global__ void mcvt_kernel(const float* __restrict__ m, __nv_bfloat16* __restrict__ mh,
                            __nv_bfloat16* __restrict__ ml)
{
    int i = (blockIdx.x * blockDim.x + threadIdx.x) * 4;
    if (i >= B_DIM * L_DIM * C_DIM) return;
    float4 v4 = *(const float4*)&m[i];
    float v[4] = { v4.x, v4.y, v4.z, v4.w };
    uint2 hi, lo;
    split4(v, hi, lo);
    *(uint2*)&mh[i] = hi;
    *(uint2*)&ml[i] = lo;
}

// ---------------- pooling ----------------
__global__ void pool_avg_kernel(const float* __restrict__ x, float* __restrict__ P0,
                                __nv_bfloat16* __restrict__ Ph, __nv_bfloat16* __restrict__ Pl)
{
    int tok = blockIdx.x, b = blockIdx.y, c = threadIdx.x;
    int t = tok, n;
    if      (t < 441) { n = 21; }
    else if (t < 697) { n = 16; t -= 441; }
    else if (t < 866) { n = 13; t -= 697; }
    else              { n = 11; t -= 866; }
    int p = t / n, q = t - p * n;
    int hs = (p * 64) / n, he = ((p + 1) * 64 + n - 1) / n;
    int ws = (q * 64) / n, we = ((q + 1) * 64 + n - 1) / n;
    float s = 0.f;
    for (int h = hs; h < he; h++) {
        const float* xr = x + (((size_t)b * 4096) + (size_t)h * 64) * C_DIM + c;
        for (int w = ws; w < we; w++) s += xr[(size_t)w * C_DIM];
    }
    float v = s / (float)((he - hs) * (we - ws));
    size_t o = ((size_t)b * NP + tok) * C_DIM + c;
    P0[o] = v;
    __nv_bfloat16 h16 = __float2bfloat16(v);
    Ph[o] = h16; Pl[o] = __float2bfloat16(v - __bfloat162float(h16));
}

__global__ void pool_max_kernel(const float* __restrict__ x, float* __restrict__ P0,
                                __nv_bfloat16* __restrict__ Ph, __nv_bfloat16* __restrict__ Pl)
{
    int t = blockIdx.x, b = blockIdx.y, c = threadIdx.x;
    int p = t >> 4, q = t & 15;
    float mx = -1e30f;
    for (int h = p * 4; h < p * 4 + 4; h++) {
        const float* xr = x + (((size_t)b * 4096) + (size_t)h * 64) * C_DIM + c;
        for (int w = q * 4; w < q * 4 + 4; w++) mx = fmaxf(mx, xr[(size_t)w * C_DIM]);
    }
    size_t o = ((size_t)b * NP + OFF_MX + t) * C_DIM + c;
    P0[o] = mx;
    __nv_bfloat16 h16 = __float2bfloat16(mx);
    Ph[o] = h16; Pl[o] = __float2bfloat16(mx - __bfloat162float(h16));
}

// =====================================================================
// Shared GEMM mainloop pieces (bf16x3, 128x128 tile, K=512)
// =====================================================================
#define STG0    4096
#define STG_SZ  40960
#define TG_SMEM (4096 + 2 * 40960)
#define CPITCH  136

// =====================================================================
// cgemm: combined conv-residual (branches 0..4) + Wq (branch 5) launch.
// grid = (4, 143). Tile map (row tiles of 128):
//   [0,28) b0 M=3528 | [28,44) b1 2048 | [44,55) b2 1352 | [55,63) b3 968
//   [63,79) b4 2048 | [79,143) Wq 8192
// =====================================================================
__global__ __launch_bounds__(256) void cgemm_kernel(
    const __nv_bfloat16* __restrict__ P0h, const __nv_bfloat16* __restrict__ P0l,
    const __nv_bfloat16* __restrict__ mh,  const __nv_bfloat16* __restrict__ ml,
    const __nv_bfloat16* __restrict__ Wth, const __nv_bfloat16* __restrict__ Wtl,
    const float* bp0, const float* bp1, const float* bp2, const float* bp3, const float* bp4,
    const float* __restrict__ P0, float* __restrict__ P1,
    __nv_bfloat16* __restrict__ Qh, __nv_bfloat16* __restrict__ Ql)
{
    extern __shared__ char sm_raw[];
    const __nv_bfloat16** aptrs = (const __nv_bfloat16**)(sm_raw + 16);
    uint32_t sb = smem_u32(sm_raw);

    int tid = threadIdx.x;
    int ti = blockIdx.y;
    int branch, tstart;
    if      (ti < 28) { branch = 0; tstart = 0;  }
    else if (ti < 44) { branch = 1; tstart = 28; }
    else if (ti < 55) { branch = 2; tstart = 44; }
    else if (ti < 63) { branch = 3; tstart = 55; }
    else if (ti < 79) { branch = 4; tstart = 63; }
    else              { branch = 5; tstart = 79; }
    const int npx_t[6]  = { 441, 256, 169, 121, 256, 0 };
    const int toff_t[6] = { 0, 441, 697, 866, 987, 0 };
    int npx = npx_t[branch], toffc = toff_t[branch];
    int M = (branch < 5) ? 8 * npx : 8192;
    int brow = (ti - tstart) * 128;
    int bcol = blockIdx.x * 128;
    const float* bias = (branch == 0) ? bp0 : (branch == 1) ? bp1 : (branch == 2) ? bp2 :
                        (branch == 3) ? bp3 : (branch == 4) ? bp4 : nullptr;
    const __nv_bfloat16* Bh = Wth + (size_t)branch * WSLOT;
    const __nv_bfloat16* Bl = Wtl + (size_t)branch * WSLOT;

    if (tid < 128) {
        int arow = brow + tid;
        if (arow >= M) arow = M - 1;
        const __nv_bfloat16 *ph, *pl;
        if (branch < 5) {
            int b = arow / npx, t = arow - (arow / npx) * npx;
            size_t o = ((size_t)b * NP + toffc + t) * 512;
            ph = P0h + o; pl = P0l + o;
        } else {
            size_t o = (size_t)arow * 512;
            ph = mh + o; pl = ml + o;
        }
        aptrs[tid] = ph; aptrs[128 + tid] = pl;
    }
    __syncthreads();

    int wid = tid >> 5;
    int wm = wid & 1, wn = wid >> 1;

    wmma::fragment<wmma::accumulator, 16, 16, 16, float> acc[4][2];
#pragma unroll
    for (int mi = 0; mi < 4; mi++)
#pragma unroll
        for (int ni = 0; ni < 2; ni++)
            wmma::fill_fragment(acc[mi][ni], 0.f);

    {
        uint32_t st = sb + STG0;
#pragma unroll
        for (int w = 0; w < 8; w++) {
            int ci = tid + w * 256;
            int region = ci >> 9, idx = ci & 511;
            int row = idx >> 2, ch = idx & 3;
            const __nv_bfloat16* src;
            if (region < 2) src = aptrs[region * 128 + row] + ch * 8;
            else            src = ((region == 2) ? Bh : Bl) + (size_t)(bcol + row) * 512 + ch * 8;
            cp16(st + region * 10240 + row * 80 + ch * 16, src);
        }
        CP_COMMIT();
    }

    for (int j = 0; j < 16; j++) {
        if (j + 1 < 16) {
            uint32_t st = sb + STG0 + ((j + 1) & 1) * STG_SZ;
            int koff = (j + 1) * 32;
#pragma unroll
            for (int w = 0; w < 8; w++) {
                int ci = tid + w * 256;
                int region = ci >> 9, idx = ci & 511;
                int row = idx >> 2, ch = idx & 3;
                const __nv_bfloat16* src;
                if (region < 2) src = aptrs[region * 128 + row] + koff + ch * 8;
                else            src = ((region == 2) ? Bh : Bl) + (size_t)(bcol + row) * 512 + koff + ch * 8;
                cp16(st + region * 10240 + row * 80 + ch * 16, src);
            }
            CP_COMMIT();
            CP_WAIT1();
        } else {
            CP_WAIT0();
        }
        __syncthreads();

        const __nv_bfloat16* st = (const __nv_bfloat16*)(sm_raw + STG0 + (j & 1) * STG_SZ);
        const __nv_bfloat16* As_h = st;
        const __nv_bfloat16* As_l = st + 5120;
        const __nv_bfloat16* Bs_h = st + 10240;
        const __nv_bfloat16* Bs_l = st + 15360;

#pragma unroll
        for (int kk = 0; kk < 2; kk++) {
            wmma::fragment<wmma::matrix_a, 16, 16, 16, __nv_bfloat16, wmma::row_major> fah[4], fal[4];
            wmma::fragment<wmma::matrix_b, 16, 16, 16, __nv_bfloat16, wmma::col_major> fbh[2], fbl[2];
#pragma unroll
            for (int mi = 0; mi < 4; mi++) {
                int r = wm * 64 + mi * 16;
                wmma::load_matrix_sync(fah[mi], As_h + r * 40 + kk * 16, 40);
                wmma::load_matrix_sync(fal[mi], As_l + r * 40 + kk * 16, 40);
            }
#pragma unroll
            for (int ni = 0; ni < 2; ni++) {
                int c = wn * 32 + ni * 16;
                wmma::load_matrix_sync(fbh[ni], Bs_h + c * 40 + kk * 16, 40);
                wmma::load_matrix_sync(fbl[ni], Bs_l + c * 40 + kk * 16, 40);
            }
#pragma unroll
            for (int mi = 0; mi < 4; mi++)
#pragma unroll
                for (int ni = 0; ni < 2; ni++) {
                    wmma::mma_sync(acc[mi][ni], fah[mi], fbh[ni], acc[mi][ni]);
                    wmma::mma_sync(acc[mi][ni], fah[mi], fbl[ni], acc[mi][ni]);
                    wmma::mma_sync(acc[mi][ni], fal[mi], fbh[ni], acc[mi][ni]);
                }
        }
        __syncthreads();
    }

    float* Cs = (float*)(sm_raw + STG0);
#pragma unroll
    for (int mi = 0; mi < 4; mi++)
#pragma unroll
        for (int ni = 0; ni < 2; ni++)
            wmma::store_matrix_sync(Cs + (wm * 64 + mi * 16) * CPITCH + wn * 32 + ni * 16,
                                    acc[mi][ni], CPITCH, wmma::mem_row_major);
    __syncthreads();

    int lane = tid & 31, wrow = tid >> 5;
    for (int rr = wrow; rr < 128; rr += 8) {
        int r = brow + rr;
        if (r >= M) continue;
        int col0 = lane * 4;
        float4 o = *(float4*)&Cs[rr * CPITCH + col0];
        int col = bcol + col0;
        if (branch < 5) {
            o.x += bias[col];     o.y += bias[col + 1];
            o.z += bias[col + 2]; o.w += bias[col + 3];
            int b = r / npx, t = r - (r / npx) * npx;
            size_t g = ((size_t)b * NP + toffc + t) * 512;
            float4 rv = *(const float4*)&P0[g + col];
            o.x += rv.x; o.y += rv.y; o.z += rv.z; o.w += rv.w;
            *(float4*)&P1[g + col] = o;
        } else {
            size_t g = (size_t)r * 512 + col;
            float vv[4] = { o.x, o.y, o.z, o.w };
            uint2 hi, lo;
            split4(vv, hi, lo);
            *(uint2*)&Qh[g] = hi;
            *(uint2*)&Ql[g] = lo;
        }
    }
}

// =====================================================================
// tgemm: generic (Wkv mode 2, Wp mode 0) — same mainloop
// =====================================================================
__global__ __launch_bounds__(256) void tgemm_kernel(
    const __nv_bfloat16* __restrict__ Ah, const __nv_bfloat16* __restrict__ Al,
    const __nv_bfloat16* __restrict__ A2h, const __nv_bfloat16* __restrict__ A2l,
    const __nv_bfloat16* __restrict__ Bh, const __nv_bfloat16* __restrict__ Bl,
    const float* __restrict__ bias,
    float* __restrict__ Cout,
    __nv_bfloat16* __restrict__ outh, __nv_bfloat16* __restrict__ outl,
    int M, int N, int mode)
{
    extern __shared__ char sm_raw[];
    const __nv_bfloat16** aptrs = (const __nv_bfloat16**)(sm_raw + 16);
    uint32_t sb = smem_u32(sm_raw);

    int tid = threadIdx.x;
    int brow = blockIdx.y * 128, bcol = blockIdx.x * 128;

    if (tid < 128) {
        int arow = brow + tid;
        if (arow >= M) arow = M - 1;
        const __nv_bfloat16 *ph, *pl;
        if (mode == 0) {
            size_t o = (size_t)arow * 512; ph = Ah + o; pl = Al + o;
        } else {
            int b = arow / NTOK, t = arow - (arow / NTOK) * NTOK;
            if (t < NP) { size_t o = ((size_t)b * NP + t) * 512; ph = Ah + o; pl = Al + o; }
            else        { size_t o = ((size_t)b * L_DIM + (t - NP)) * 512; ph = A2h + o; pl = A2l + o; }
        }
        aptrs[tid] = ph; aptrs[128 + tid] = pl;
    }
    __syncthreads();

    int wid = tid >> 5;
    int wm = wid & 1, wn = wid >> 1;

    wmma::fragment<wmma::accumulator, 16, 16, 16, float> acc[4][2];
#pragma unroll
    for (int mi = 0; mi < 4; mi++)
#pragma unroll
        for (int ni = 0; ni < 2; ni++)
            wmma::fill_fragment(acc[mi][ni], 0.f);

    {
        uint32_t st = sb + STG0;
#pragma unroll
        for (int w = 0; w < 8; w++) {
            int ci = tid + w * 256;
            int region = ci >> 9, idx = ci & 511;
            int row = idx >> 2, ch = idx & 3;
            const __nv_bfloat16* src;
            if (region < 2) src = aptrs[region * 128 + row] + ch * 8;
            else            src = ((region == 2) ? Bh : Bl) + (size_t)(bcol + row) * 512 + ch * 8;
            cp16(st + region * 10240 + row * 80 + ch * 16, src);
        }
        CP_COMMIT();
    }

    for (int j = 0; j < 16; j++) {
        if (j + 1 < 16) {
            uint32_t st = sb + STG0 + ((j + 1) & 1) * STG_SZ;
            int koff = (j + 1) * 32;
#pragma unroll
            for (int w = 0; w < 8; w++) {
                int ci = tid + w * 256;
                int region = ci >> 9, idx = ci & 511;
                int row = idx >> 2, ch = idx & 3;
                const __nv_bfloat16* src;
                if (region < 2) src = aptrs[region * 128 + row] + koff + ch * 8;
                else            src = ((region == 2) ? Bh : Bl) + (size_t)(bcol + row) * 512 + koff + ch * 8;
                cp16(st + region * 10240 + row * 80 + ch * 16, src);
            }
            CP_COMMIT();
            CP_WAIT1();
        } else {
            CP_WAIT0();
        }
        __syncthreads();

        const __nv_bfloat16* st = (const __nv_bfloat16*)(sm_raw + STG0 + (j & 1) * STG_SZ);
        const __nv_bfloat16* As_h = st;
        const __nv_bfloat16* As_l = st + 5120;
        const __nv_bfloat16* Bs_h = st + 10240;
        const __nv_bfloat16* Bs_l = st + 15360;

#pragma unroll
        for (int kk = 0; kk < 2; kk++) {
            wmma::fragment<wmma::matrix_a, 16, 16, 16, __nv_bfloat16, wmma::row_major> fah[4], fal[4];
            wmma::fragment<wmma::matrix_b, 16, 16, 16, __nv_bfloat16, wmma::col_major> fbh[2], fbl[2];
#pragma unroll
            for (int mi = 0; mi < 4; mi++) {
                int r = wm * 64 + mi * 16;
                wmma::load_matrix_sync(fah[mi], As_h + r * 40 + kk * 16, 40);
                wmma::load_matrix_sync(fal[mi], As_l + r * 40 + kk * 16, 40);
            }
#pragma unroll
            for (int ni = 0; ni < 2; ni++) {
                int c = wn * 32 + ni * 16;
                wmma::load_matrix_sync(fbh[ni], Bs_h + c * 40 + kk * 16, 40);
                wmma::load_matrix_sync(fbl[ni], Bs_l + c * 40 + kk * 16, 40);
            }
#pragma unroll
            for (int mi = 0; mi < 4; mi++)
#pragma unroll
                for (int ni = 0; ni < 2; ni++) {
                    wmma::mma_sync(acc[mi][ni], fah[mi], fbh[ni], acc[mi][ni]);
                    wmma::mma_sync(acc[mi][ni], fah[mi], fbl[ni], acc[mi][ni]);
                    wmma::mma_sync(acc[mi][ni], fal[mi], fbh[ni], acc[mi][ni]);
                }
        }
        __syncthreads();
    }

    float* Cs = (float*)(sm_raw + STG0);
#pragma unroll
    for (int mi = 0; mi < 4; mi++)
#pragma unroll
        for (int ni = 0; ni < 2; ni++)
            wmma::store_matrix_sync(Cs + (wm * 64 + mi * 16) * CPITCH + wn * 32 + ni * 16,
                                    acc[mi][ni], CPITCH, wmma::mem_row_major);
    __syncthreads();

    int lane = tid & 31, wrow = tid >> 5;
    for (int rr = wrow; rr < 128; rr += 8) {
        int r = brow + rr;
        if (r >= M) continue;
        int col0 = lane * 4;
        float4 o = *(float4*)&Cs[rr * CPITCH + col0];
        int col = bcol + col0;
        if (bias) {
            o.x += bias[col];     o.y += bias[col + 1];
            o.z += bias[col + 2]; o.w += bias[col + 3];
        }
        if (outh) {
            size_t g = (size_t)r * N + col;
            float vv[4] = { o.x, o.y, o.z, o.w };
            uint2 hi, lo;
            split4(vv, hi, lo);
            *(uint2*)&outh[g] = hi;
            *(uint2*)&outl[g] = lo;
        } else {
            *(float4*)&Cout[(size_t)r * N + col] = o;
        }
    }
}

// ---------------- mx copy ----------------
__global__ void mx_copy_kernel(const float* __restrict__ P1, float* __restrict__ out2)
{
    int idx = blockIdx.x * blockDim.x + threadIdx.x;
    if (idx >= B_DIM * C_DIM * 256) return;
    int t = idx & 255, c = (idx >> 8) & 511, b = idx >> 17;
    out2[idx] = P1[(((size_t)b * NP) + OFF_MX + t) * C_DIM + c];
}

// ---------------- layernorm -> bf16 hi/lo ----------------
__global__ void ln_kernel(const float* __restrict__ X, const float* __restrict__ g,
                          const float* __restrict__ be,
                          __nv_bfloat16* __restrict__ Yh, __nv_bfloat16* __restrict__ Yl)
{
    int row = blockIdx.x, tid = threadIdx.x;
    float4 v = ((const float4*)(X + (size_t)row * C_DIM))[tid];
    float s  = v.x + v.y + v.z + v.w;
    float s2 = v.x * v.x + v.y * v.y + v.z * v.z + v.w * v.w;
#pragma unroll
    for (int o = 16; o >= 1; o >>= 1) {
        s  += __shfl_xor_sync(0xffffffffu, s,  o);
        s2 += __shfl_xor_sync(0xffffffffu, s2, o);
    }
    __shared__ float ws[4], ws2[4];
    int wid = tid >> 5, lane = tid & 31;
    if (lane == 0) { ws[wid] = s; ws2[wid] = s2; }
    __syncthreads();
    float ts = ws[0] + ws[1] + ws[2] + ws[3], ts2 = ws2[0] + ws2[1] + ws2[2] + ws2[3];
    float mean = ts * (1.f / C_DIM);
    float var  = ts2 * (1.f / C_DIM) - mean * mean;
    float rstd = rsqrtf(var + LN_EPS);
    float4 gg = ((const float4*)g)[tid], bb = ((const float4*)be)[tid];
    float y[4] = { (v.x - mean) * rstd * gg.x + bb.x, (v.y - mean) * rstd * gg.y + bb.y,
                   (v.z - mean) * rstd * gg.z + bb.z, (v.w - mean) * rstd * gg.w + bb.w };
    size_t o = (size_t)row * C_DIM + tid * 4;
    uint2 hi, lo;
    split4(y, hi, lo);
    *(uint2*)&Yh[o] = hi;
    *(uint2*)&Yl[o] = lo;
}

// =====================================================================
// wmma flash attention, bf16x3, fused alpha-accumulate.
// =====================================================================
#define QP 72
#define SP 68
#define ATT_SMEM (8 * 64 * QP * 2 + 2 * 64 * SP * 4)   // 108544

__global__ __launch_bounds__(256) void attn_wmma_kernel(
    const __nv_bfloat16* __restrict__ Qh, const __nv_bfloat16* __restrict__ Ql,
    const __nv_bfloat16* __restrict__ KVh, const __nv_bfloat16* __restrict__ KVl,
    __nv_bfloat16* __restrict__ Oh, __nv_bfloat16* __restrict__ Ol)
{
    extern __shared__ char smc[];
    __nv_bfloat16* sQh = (__nv_bfloat16*)smc;
    __nv_bfloat16* sQl = sQh + 64 * QP;
    __nv_bfloat16* sKh = sQl + 64 * QP;
    __nv_bfloat16* sKl = sKh + 64 * QP;
    __nv_bfloat16* sVh = sKl + 64 * QP;
    __nv_bfloat16* sVl = sVh + 64 * QP;
    __nv_bfloat16* sPh = sVl + 64 * QP;
    __nv_bfloat16* sPl = sPh + 64 * QP;
    float* Ss = (float*)(sPl + 64 * QP);   // [64][68]
    float* Oa = Ss + 64 * SP;              // [64][68]

    int tid = threadIdx.x;
    int b = blockIdx.z, h = blockIdx.y, l0 = blockIdx.x * 64;
    int warp = tid >> 5;
    int wm = (warp & 1) * 32, wn = (warp >> 1) * 16;
    int ty = tid >> 4, tx = tid & 15;
    const float scale = 0.125f;

#pragma unroll
    for (int w = 0; w < 4; w++) {
        int ci = tid + w * 256;
        int arr = ci >> 9, idx = ci & 511;
        int row = idx >> 3, ch = idx & 7;
        const __nv_bfloat16* src = (arr ? Ql : Qh) +
            (((size_t)b * L_DIM) + l0 + row) * 512 + h * 64 + ch * 8;
        cp16(smem_u32((arr ? sQl : sQh) + row * QP + ch * 8), src);
    }
    CP_COMMIT();

    for (int i = tid; i < 64 * SP; i += 256) Oa[i] = 0.f;
    float mrow[4] = { -1e30f, -1e30f, -1e30f, -1e30f };
    float lrow[4] = {};

    // issue KV tile 0
    {
#pragma unroll
        for (int w = 0; w < 8; w++) {
            int ci = tid + w * 256;
            int arr = ci >> 9, idx = ci & 511;
            int row = idx >> 3, ch = idx & 7;
            int kg = row;  // kt=0
            const __nv_bfloat16* gb = (arr & 1) ? KVl : KVh;
            size_t off = (((size_t)b * NTOK) + kg) * 1024 + (arr >> 1) * 512 + h * 64 + ch * 8;
            __nv_bfloat16* dstb = (arr == 0) ? sKh : (arr == 1) ? sKl : (arr == 2) ? sVh : sVl;
            cp16(smem_u32(dstb + row * QP + ch * 8), gb + off);
        }
        CP_COMMIT();
    }

    for (int kt = 0; kt < 36; kt++) {
        int kbase = kt * 64;
        CP_WAIT0();
        __syncthreads();

        // ---- S = Q K^T ----
        {
            wmma::fragment<wmma::accumulator, 16, 16, 16, float> sf[2];
            wmma::fill_fragment(sf[0], 0.f);
            wmma::fill_fragment(sf[1], 0.f);
#pragma unroll
            for (int k = 0; k < 4; k++) {
                wmma::fragment<wmma::matrix_b, 16, 16, 16, __nv_bfloat16, wmma::col_major> fbh, fbl;
                wmma::load_matrix_sync(fbh, sKh + wn * QP + k * 16, QP);
                wmma::load_matrix_sync(fbl, sKl + wn * QP + k * 16, QP);
#pragma unroll
                for (int mi = 0; mi < 2; mi++) {
                    wmma::fragment<wmma::matrix_a, 16, 16, 16, __nv_bfloat16, wmma::row_major> fah, fal;
                    wmma::load_matrix_sync(fah, sQh + (wm + mi * 16) * QP + k * 16, QP);
                    wmma::load_matrix_sync(fal, sQl + (wm + mi * 16) * QP + k * 16, QP);
                    wmma::mma_sync(sf[mi], fah, fbh, sf[mi]);
                    wmma::mma_sync(sf[mi], fah, fbl, sf[mi]);
                    wmma::mma_sync(sf[mi], fal, fbh, sf[mi]);
                }
            }
            wmma::store_matrix_sync(Ss + wm * SP + wn, sf[0], SP, wmma::mem_row_major);
            wmma::store_matrix_sync(Ss + (wm + 16) * SP + wn, sf[1], SP, wmma::mem_row_major);
        }
        __syncthreads();

        // ---- scalar online softmax ----
        float s[4][4], tmax[4];
#pragma unroll
        for (int i = 0; i < 4; i++) {
            float4 sv = *(const float4*)&Ss[(ty * 4 + i) * SP + tx * 4];
            s[i][0] = sv.x; s[i][1] = sv.y; s[i][2] = sv.z; s[i][3] = sv.w;
            tmax[i] = -1e30f;
#pragma unroll
            for (int j = 0; j < 4; j++) {
                int cg = kbase + tx * 4 + j;
                s[i][j] = (cg < NTOK) ? s[i][j] * scale : -1e30f;
                tmax[i] = fmaxf(tmax[i], s[i][j]);
            }
        }
#pragma unroll
        for (int i = 0; i < 4; i++)
#pragma unroll
            for (int o = 8; o >= 1; o >>= 1)
                tmax[i] = fmaxf(tmax[i], __shfl_xor_sync(0xffffffffu, tmax[i], o));
        float alpha[4], rsum[4];
#pragma unroll
        for (int i = 0; i < 4; i++) {
            float mnew = fmaxf(mrow[i], tmax[i]);
            alpha[i] = __expf(mrow[i] - mnew);
            mrow[i] = mnew;
            float rs = 0.f;
#pragma unroll
            for (int j = 0; j < 4; j++) {
                float p = (s[i][j] > -1e29f) ? __expf(s[i][j] - mnew) : 0.f;
                s[i][j] = p; rs += p;
            }
            rsum[i] = rs;
            lrow[i] = lrow[i] * alpha[i];
        }
#pragma unroll
        for (int i = 0; i < 4; i++) {
#pragma unroll
            for (int o = 8; o >= 1; o >>= 1)
                rsum[i] += __shfl_xor_sync(0xffffffffu, rsum[i], o);
            lrow[i] += rsum[i];
        }
        // write P hi/lo (vectorized)
#pragma unroll
        for (int i = 0; i < 4; i++) {
            int r = ty * 4 + i;
            uint2 hi, lo;
            split4(s[i], hi, lo);
            *(uint2*)&sPh[r * QP + tx * 4] = hi;
            *(uint2*)&sPl[r * QP + tx * 4] = lo;
        }
        __syncthreads();

        // ---- O_tile = P V ----
        {
            wmma::fragment<wmma::accumulator, 16, 16, 16, float> of[2];
            wmma::fill_fragment(of[0], 0.f);
            wmma::fill_fragment(of[1], 0.f);
#pragma unroll
            for (int k = 0; k < 4; k++) {
                wmma::fragment<wmma::matrix_b, 16, 16, 16, __nv_bfloat16, wmma::row_major> fbh, fbl;
                wmma::load_matrix_sync(fbh, sVh + k * 16 * QP + wn, QP);
                wmma::load_matrix_sync(fbl, sVl + k * 16 * QP + wn, QP);
#pragma unroll
                for (int mi = 0; mi < 2; mi++) {
                    wmma::fragment<wmma::matrix_a, 16, 16, 16, __nv_bfloat16, wmma::row_major> fah, fal;
                    wmma::load_matrix_sync(fah, sPh + (wm + mi * 16) * QP + k * 16, QP);
                    wmma::load_matrix_sync(fal, sPl + (wm + mi * 16) * QP + k * 16, QP);
                    wmma::mma_sync(of[mi], fah, fbh, of[mi]);
                    wmma::mma_sync(of[mi], fah, fbl, of[mi]);
                    wmma::mma_sync(of[mi], fal, fbh, of[mi]);
                }
            }
            wmma::store_matrix_sync(Ss + wm * SP + wn, of[0], SP, wmma::mem_row_major);
            wmma::store_matrix_sync(Ss + (wm + 16) * SP + wn, of[1], SP, wmma::mem_row_major);
        }
        __syncthreads();

        // issue next KV tile before the accumulate (overlap)
        if (kt + 1 < 36) {
            int nbase = (kt + 1) * 64;
#pragma unroll
            for (int w = 0; w < 8; w++) {
                int ci = tid + w * 256;
                int arr = ci >> 9, idx = ci & 511;
                int row = idx >> 3, ch = idx & 7;
                int kg = nbase + row;
                const __nv_bfloat16* gb = (arr & 1) ? KVl : KVh;
                size_t off = (((size_t)b * NTOK) + (kg < NTOK ? kg : 0)) * 1024
                           + (arr >> 1) * 512 + h * 64 + ch * 8;
                __nv_bfloat16* dstb = (arr == 0) ? sKh : (arr == 1) ? sKl : (arr == 2) ? sVh : sVl;
                cp16z(smem_u32(dstb + row * QP + ch * 8), gb + off, (kg < NTOK) ? 16 : 0);
            }
            CP_COMMIT();
        }

        // fused rescale + accumulate
#pragma unroll
        for (int i = 0; i < 4; i++) {
            int r = ty * 4 + i;
            float4 ov = *(float4*)&Oa[r * SP + tx * 4];
            float4 tv = *(const float4*)&Ss[r * SP + tx * 4];
            ov.x = ov.x * alpha[i] + tv.x; ov.y = ov.y * alpha[i] + tv.y;
            ov.z = ov.z * alpha[i] + tv.z; ov.w = ov.w * alpha[i] + tv.w;
            *(float4*)&Oa[r * SP + tx * 4] = ov;
        }
        // NOTE: next loop's CP_WAIT0+syncthreads orders accumulate before S store.
    }

    // normalize + store bf16 hi/lo (vectorized)
#pragma unroll
    for (int i = 0; i < 4; i++) {
        float inv = 1.f / lrow[i];
        int r = ty * 4 + i;
        size_t o = (((size_t)b * L_DIM) + l0 + r) * C_DIM + h * HD + tx * 4;
        float vv[4];
#pragma unroll
        for (int j = 0; j < 4; j++) vv[j] = Oa[r * SP + tx * 4 + j] * inv;
        uint2 hi, lo;
        split4(vv, hi, lo);
        *(uint2*)&Oh[o] = hi;
        *(uint2*)&Ol[o] = lo;
    }
}

// ---------------- launch ----------------
extern "C" void kernel_launch(void* const* d_in, const int* in_sizes, int n_in,
                              void* d_out, int out_size)
{
    const float* x    = (const float*)d_in[0];
    const float* m    = (const float*)d_in[1];
    const float* wsrc5[5] = { (const float*)d_in[2], (const float*)d_in[4], (const float*)d_in[6],
                              (const float*)d_in[8], (const float*)d_in[10] };
    const float* bsrc5[5] = { (const float*)d_in[3], (const float*)d_in[5], (const float*)d_in[7],
                              (const float*)d_in[9], (const float*)d_in[11] };
    const float* ln_g = (const float*)d_in[12];
    const float* ln_b = (const float*)d_in[13];
    const float* Wq   = (const float*)d_in[14];
    const float* Wkv  = (const float*)d_in[15];
    const float* Wp   = (const float*)d_in[16];
    const float* bp   = (const float*)d_in[17];
    float* out  = (float*)d_out;
    float* out2 = (float*)d_out + (size_t)B_DIM * L_DIM * C_DIM;

    float *P0, *P1;
    __nv_bfloat16 *P0h, *P0l, *P2h, *P2l, *mh, *ml, *Qh, *Ql, *KVh, *KVl, *Oh, *Ol, *Wth, *Wtl;
    cudaGetSymbolAddress((void**)&P0,  g_P0);
    cudaGetSymbolAddress((void**)&P1,  g_P1);
    cudaGetSymbolAddress((void**)&P0h, g_P0h);
    cudaGetSymbolAddress((void**)&P0l, g_P0l);
    cudaGetSymbolAddress((void**)&P2h, g_P2h);
    cudaGetSymbolAddress((void**)&P2l, g_P2l);
    cudaGetSymbolAddress((void**)&mh,  g_mh);
    cudaGetSymbolAddress((void**)&ml,  g_ml);
    cudaGetSymbolAddress((void**)&Qh,  g_Qh);
    cudaGetSymbolAddress((void**)&Ql,  g_Ql);
    cudaGetSymbolAddress((void**)&KVh, g_KVh);
    cudaGetSymbolAddress((void**)&KVl, g_KVl);
    cudaGetSymbolAddress((void**)&Oh,  g_Oh);
    cudaGetSymbolAddress((void**)&Ol,  g_Ol);
    cudaGetSymbolAddress((void**)&Wth, g_Wth);
    cudaGetSymbolAddress((void**)&Wtl, g_Wtl);

    cudaFuncSetAttribute(cgemm_kernel,     cudaFuncAttributeMaxDynamicSharedMemorySize, TG_SMEM);
    cudaFuncSetAttribute(tgemm_kernel,     cudaFuncAttributeMaxDynamicSharedMemorySize, TG_SMEM);
    cudaFuncSetAttribute(attn_wmma_kernel, cudaFuncAttributeMaxDynamicSharedMemorySize, ATT_SMEM);

    wsplit8_kernel<<<dim3(32, 16, 8), dim3(32, 8)>>>(
        wsrc5[0], wsrc5[1], wsrc5[2], wsrc5[3], wsrc5[4], Wq, Wp, Wkv, Wth, Wtl);
    mcvt_kernel<<<(B_DIM * L_DIM * C_DIM / 4 + 255) / 256, 256>>>(m, mh, ml);

    pool_avg_kernel<<<dim3(987, B_DIM), 512>>>(x, P0, P0h, P0l);
    pool_max_kernel<<<dim3(256, B_DIM), 512>>>(x, P0, P0h, P0l);

    // combined conv-residual x5 + Wq
    cgemm_kernel<<<dim3(4, 143), 256, TG_SMEM>>>(
        P0h, P0l, mh, ml, Wth, Wtl,
        bsrc5[0], bsrc5[1], bsrc5[2], bsrc5[3], bsrc5[4],
        P0, P1, Qh, Ql);

    mx_copy_kernel<<<(B_DIM * C_DIM * 256 + 255) / 256, 256>>>(P1, out2);
    ln_kernel<<<B_DIM * NP, 128>>>(P1, ln_g, ln_b, P2h, P2l);

    // kv = [p; m] @ Wkv  -> bf16 hi/lo
    tgemm_kernel<<<dim3(8, (B_DIM * NTOK + 127) / 128), 256, TG_SMEM>>>(
        P2h, P2l, mh, ml, Wth + 7 * (size_t)WSLOT, Wtl + 7 * (size_t)WSLOT,
        nullptr, nullptr, KVh, KVl, B_DIM * NTOK, 1024, 2);

    // attention
    attn_wmma_kernel<<<dim3(L_DIM / 64, NH, B_DIM), 256, ATT_SMEM>>>(Qh, Ql, KVh, KVl, Oh, Ol);

    // out = O @ Wp + bp (f32)
    tgemm_kernel<<<dim3(4, 64), 256, TG_SMEM>>>(
        Oh, Ol, nullptr, nullptr, Wth + 6 * (size_t)WSLOT, Wtl + 6 * (size_t)WSLOT,
        bp, out, nullptr, nullptr, B_DIM * L_DIM, 512, 0);
}